// round 13
// baseline (speedup 1.0000x reference)
#include <cuda_runtime.h>
#include <cuda_fp16.h>
#include <math.h>
#include <stdint.h>

#define L_TOK 3840
#define DIM   1536
#define NH    12
#define HD    128
#define FRAME 480
#define NPAIR 64
#define N_QB  30
#define N_ITEM (N_QB * NH)

// ---------------- device scratch (no allocs allowed) ----------------
__device__ float g_q[L_TOK * DIM];
__device__ float g_k[L_TOK * DIM];
__device__ float g_cos[L_TOK * NPAIR];
__device__ float g_sin[L_TOK * NPAIR];
__device__ int   g_work[4];               // 0: qkv gemm, 1: attention, 2: o gemm
__device__ __half g_ah[L_TOK * DIM];      // A hi (x, later attn out)
__device__ __half g_al[L_TOK * DIM];      // A lo
__device__ __half g_wh[4][DIM * DIM];     // W^T fp16 (single) for q,k,v,o
__device__ __half g_qh[L_TOK * DIM];
__device__ __half g_ql[L_TOK * DIM];
__device__ __half g_kh[L_TOK * DIM];      // K single fp16
__device__ __half g_vh[L_TOK * DIM];      // V single fp16

// =================== sm_80-era PTX helpers (valid on plain sm_103) ==========
__device__ __forceinline__ uint32_t smem_u32(const void* p) {
    uint32_t a;
    asm("{ .reg .u64 t; cvta.to.shared.u64 t, %1; cvt.u32.u64 %0, t; }" : "=r"(a) : "l"(p));
    return a;
}
#define CP_ASYNC16(dst, src) \
    asm volatile("cp.async.cg.shared.global [%0], [%1], 16;" :: "r"(dst), "l"(src))
#define CP_COMMIT() asm volatile("cp.async.commit_group;" ::: "memory")
#define CP_WAIT1()  asm volatile("cp.async.wait_group 1;" ::: "memory")
#define CP_WAIT0()  asm volatile("cp.async.wait_group 0;" ::: "memory")

__device__ __forceinline__ void ldsm4(uint32_t* r, uint32_t addr) {
    asm volatile("ldmatrix.sync.aligned.m8n8.x4.shared.b16 {%0,%1,%2,%3}, [%4];"
                 : "=r"(r[0]), "=r"(r[1]), "=r"(r[2]), "=r"(r[3]) : "r"(addr));
}
__device__ __forceinline__ void ldsm4t(uint32_t* r, uint32_t addr) {
    asm volatile("ldmatrix.sync.aligned.m8n8.x4.trans.shared.b16 {%0,%1,%2,%3}, [%4];"
                 : "=r"(r[0]), "=r"(r[1]), "=r"(r[2]), "=r"(r[3]) : "r"(addr));
}
__device__ __forceinline__ void mma16816(float* c, const uint32_t* a, const uint32_t* b) {
    asm volatile("mma.sync.aligned.m16n8k16.row.col.f32.f16.f16.f32 "
                 "{%0,%1,%2,%3}, {%4,%5,%6,%7}, {%8,%9}, {%0,%1,%2,%3};"
                 : "+f"(c[0]), "+f"(c[1]), "+f"(c[2]), "+f"(c[3])
                 : "r"(a[0]), "r"(a[1]), "r"(a[2]), "r"(a[3]), "r"(b[0]), "r"(b[1]));
}
#define SWZ128(off) ((off) ^ (((off) >> 3) & 0x70))

__device__ __forceinline__ uint32_t pack_f16(float lo, float hi) {
    uint32_t r;
    asm("cvt.rn.f16x2.f32 %0, %1, %2;" : "=r"(r) : "f"(hi), "f"(lo));
    return r;
}

// ---------------- angle table ----------------
__global__ void angles_kernel(const float* __restrict__ ff,
                              const float* __restrict__ fh,
                              const float* __restrict__ fw) {
    int idx = blockIdx.x * blockDim.x + threadIdx.x;
    if (idx >= L_TOK * NPAIR) return;
    int l = idx / NPAIR, j = idx % NPAIR;
    int f = l / FRAME, r = l % FRAME;
    int h = r / 30, w = r % 30;
    float a;
    if (j < 22)      a = ff[f * 22 + j];
    else if (j < 43) a = fh[h * 21 + (j - 22)];
    else             a = fw[w * 21 + (j - 43)];
    g_cos[idx] = cosf(a);
    g_sin[idx] = sinf(a);
}

// ---------------- split fp32 -> fp16 hi/lo ----------------
__global__ __launch_bounds__(256) void split_kernel(const float* __restrict__ x,
                                                    __half* __restrict__ hi,
                                                    __half* __restrict__ lo, int n) {
    int i = blockIdx.x * blockDim.x + threadIdx.x;
    if (i * 4 >= n) return;
    float4 v = *(const float4*)&x[i * 4];
    __half h0 = __float2half(v.x), h1 = __float2half(v.y);
    __half h2 = __float2half(v.z), h3 = __float2half(v.w);
    __half l0 = __float2half(v.x - __half2float(h0));
    __half l1 = __float2half(v.y - __half2float(h1));
    __half l2 = __float2half(v.z - __half2float(h2));
    __half l3 = __float2half(v.w - __half2float(h3));
    __half2* ph = (__half2*)&hi[i * 4];
    __half2* pl = (__half2*)&lo[i * 4];
    ph[0] = {h0, h1}; ph[1] = {h2, h3};
    pl[0] = {l0, l1}; pl[1] = {l2, l3};
}

// ------- fused transpose of 4 weights [K,N] -> [N,K], single fp16 -------
__global__ __launch_bounds__(256) void transpose_half4_kernel(
    const float* __restrict__ W0, const float* __restrict__ W1,
    const float* __restrict__ W2, const float* __restrict__ W3,
    __half* __restrict__ ThBase) {
    __shared__ float t[32][33];
    int z = blockIdx.z;
    const float* W = (z == 0) ? W0 : (z == 1) ? W1 : (z == 2) ? W2 : W3;
    __half* Th = ThBase + (size_t)z * DIM * DIM;
    int tx = threadIdx.x, ty = threadIdx.y;  // 32 x 8
    int x0 = blockIdx.x * 32, y0 = blockIdx.y * 32;
#pragma unroll
    for (int i = 0; i < 32; i += 8)
        t[ty + i][tx] = W[(size_t)(y0 + ty + i) * DIM + x0 + tx];
    __syncthreads();
#pragma unroll
    for (int i = 0; i < 32; i += 8)
        Th[(size_t)(x0 + ty + i) * DIM + y0 + tx] = __float2half(t[tx][ty + i]);
}

// -------- persistent HMMA fp16 2-term GEMM: BK=128, 256t, cross-item ring ---
#define GK       128
#define TILE_B   32768
#define BUF_B    (3 * TILE_B)     // Ah, Al, Bh
#define NCH      (DIM / GK)       // 12
#define GSMEM    (1024 + 2 * BUF_B)

struct GemmArgs {
    const __half *wh0, *wh1, *wh2;
    const float *b0, *b1, *b2;
    float *o0, *o1;
    __half *ovh;                  // single fp16 output for z=2 (V)
};

__global__ __launch_bounds__(256, 1) void gemm_hmma(const __half* __restrict__ Ah,
                                                    const __half* __restrict__ Al,
                                                    GemmArgs ga, int n_item, int qkv,
                                                    int* __restrict__ counter) {
    extern __shared__ char dsm[];
    __shared__ int wslot, wnext;
    uint32_t raw = smem_u32(dsm);
    uint32_t sbase = (raw + 1023u) & ~1023u;

    int tid = threadIdx.x;
    int wid = tid >> 5, lane = tid & 31;

    int m_base = (wid & 3) * 32;
    int n_base = (wid >> 2) * 64;
    int a_r = m_base + (lane & 7) + ((lane >> 3) & 1) * 8;
    int a_g = (lane >> 4);
    int b_r = n_base + ((lane >> 4) & 1) * 8 + (lane & 7);
    int b_g = (lane >> 3) & 1;

    auto decode = [&](int it, int& m0, int& n0, const __half*& Bh,
                      const float*& bias, float*& Cf) {
        int z, rem;
        if (qkv) { z = it / 360; rem = it - z * 360; }
        else     { z = 0; rem = it; }
        int by = rem / 12, bx = rem - by * 12;
        m0 = by * 128; n0 = bx * 128;
        if (z == 0)      { Bh = ga.wh0; bias = ga.b0; Cf = ga.o0; }
        else if (z == 1) { Bh = ga.wh1; bias = ga.b1; Cf = ga.o1; }
        else             { Bh = ga.wh2; bias = ga.b2; Cf = nullptr; }
    };

    auto load_chunk = [&](int m0_, int n0_, const __half* Bh_, int c, int buf) {
        uint32_t dst0 = sbase + (uint32_t)buf * BUF_B;
        const __half* s0 = Ah + (size_t)m0_ * DIM + c * GK;
        const __half* s1 = Al + (size_t)m0_ * DIM + c * GK;
        const __half* s2 = Bh_ + (size_t)n0_ * DIM + c * GK;
        const __half* srcs[3] = {s0, s1, s2};
#pragma unroll
        for (int it = 0; it < 24; it++) {
            int idx = it * 256 + tid;
            int tile = idx >> 11;
            int rem = idx & 2047;
            int r = rem >> 4, g = rem & 15;
            const __half* src = srcs[tile] + (size_t)r * DIM + g * 8;
            uint32_t off = (uint32_t)((g >> 3) * 16384) + SWZ128((uint32_t)(r * 128 + (g & 7) * 16));
            CP_ASYNC16(dst0 + (uint32_t)tile * TILE_B + off, src);
        }
    };

    if (tid == 0) wslot = atomicAdd(counter, 1);
    __syncthreads();
    int cur = wslot;
    if (cur >= n_item) return;

    int m0, n0; const __half* Bh; const float* bias; float* Cf;
    decode(cur, m0, n0, Bh, bias, Cf);

    load_chunk(m0, n0, Bh, 0, 0); CP_COMMIT();
    load_chunk(m0, n0, Bh, 1, 1); CP_COMMIT();

    float Creg[2][8][4];
#pragma unroll
    for (int mt = 0; mt < 2; mt++)
#pragma unroll
        for (int nf = 0; nf < 8; nf++)
#pragma unroll
            for (int j = 0; j < 4; j++) Creg[mt][nf][j] = 0.f;

    for (;;) {
        for (int c = 0; c < NCH; c++) {
            CP_WAIT1();
            __syncthreads();
            if (c == 0 && tid == 0) wnext = atomicAdd(counter, 1);

            int buf = c & 1;
            uint32_t sb = sbase + (uint32_t)buf * BUF_B;
            uint32_t sAh = sb, sAl = sb + TILE_B, sBh = sb + 2 * TILE_B;

#pragma unroll
            for (int ks = 0; ks < 8; ks++) {
                uint32_t ah[2][4], al[2][4], bh[16];
#pragma unroll
                for (int mt = 0; mt < 2; mt++) {
                    uint32_t off = (uint32_t)((ks >> 2) * 16384) +
                        SWZ128((uint32_t)((a_r + mt * 16) * 128 + (((ks & 3) * 2 + a_g) * 16)));
                    ldsm4(ah[mt], sAh + off);
                    ldsm4(al[mt], sAl + off);
                }
#pragma unroll
                for (int nf2 = 0; nf2 < 4; nf2++) {
                    uint32_t off = (uint32_t)((ks >> 2) * 16384) +
                        SWZ128((uint32_t)((b_r + nf2 * 16) * 128 + (((ks & 3) * 2 + b_g) * 16)));
                    ldsm4(&bh[nf2 * 4], sBh + off);
                }
#pragma unroll
                for (int nf = 0; nf < 8; nf++)
#pragma unroll
                    for (int mt = 0; mt < 2; mt++)
                        mma16816(Creg[mt][nf], ah[mt], &bh[nf * 2]);
#pragma unroll
                for (int nf = 0; nf < 8; nf++)
#pragma unroll
                    for (int mt = 0; mt < 2; mt++)
                        mma16816(Creg[mt][nf], al[mt], &bh[nf * 2]);
            }
            __syncthreads();

            int gch = c + 2;
            if (gch < NCH) {
                load_chunk(m0, n0, Bh, gch, gch & 1);
            } else {
                int nx = wnext;   // published by syncs since c==0
                if (nx < n_item) {
                    int m2, n2; const __half* B2; const float* b2_; float* C2;
                    decode(nx, m2, n2, B2, b2_, C2);
                    load_chunk(m2, n2, B2, gch - NCH, gch & 1);
                }
            }
            CP_COMMIT();
        }

        // ---- epilogue for cur (overlaps in-flight loads of next item) ----
#pragma unroll
        for (int mt = 0; mt < 2; mt++) {
#pragma unroll
            for (int nf = 0; nf < 8; nf++) {
                int r0 = m0 + m_base + mt * 16 + (lane >> 2);
                int col = n0 + n_base + nf * 8 + (lane & 3) * 2;
                float2 bv = *(const float2*)&bias[col];
                float* cc = Creg[mt][nf];
                float c00 = cc[0] + bv.x, c01 = cc[1] + bv.y;
                float c10 = cc[2] + bv.x, c11 = cc[3] + bv.y;
                if (Cf == nullptr) {
                    *(uint32_t*)&ga.ovh[(size_t)r0 * DIM + col] = pack_f16(c00, c01);
                    *(uint32_t*)&ga.ovh[(size_t)(r0 + 8) * DIM + col] = pack_f16(c10, c11);
                } else {
                    *(float2*)&Cf[(size_t)r0 * DIM + col] = {c00, c01};
                    *(float2*)&Cf[(size_t)(r0 + 8) * DIM + col] = {c10, c11};
                }
                cc[0] = 0.f; cc[1] = 0.f; cc[2] = 0.f; cc[3] = 0.f;
            }
        }

        int nx = wnext;
        if (nx >= n_item) return;
        cur = nx;
        decode(cur, m0, n0, Bh, bias, Cf);
    }
}

// ---------------- fused RMSNorm + RoPE: q -> fp16 hi/lo, k -> fp16 single ---
__global__ __launch_bounds__(256) void rmsnorm_rope_split2(
    const float* __restrict__ xq, const float* __restrict__ xk,
    const float* __restrict__ gqv, const float* __restrict__ gkv,
    __half* __restrict__ qh, __half* __restrict__ ql,
    __half* __restrict__ kh) {
    int row = blockIdx.x;
    int which = blockIdx.y;
    const float* xp = (which ? xk : xq) + (size_t)row * DIM;
    const float* g = which ? gkv : gqv;
    float outscale = which ? 1.0f : 0.08838834764831845f;
    int tid = threadIdx.x;

    float ss = 0.f;
    for (int i = tid; i < DIM; i += 256) {
        float v = xp[i];
        ss += v * v;
    }
    __shared__ float red[8];
#pragma unroll
    for (int m = 16; m; m >>= 1) ss += __shfl_xor_sync(0xffffffffu, ss, m);
    if ((tid & 31) == 0) red[tid >> 5] = ss;
    __syncthreads();
    if (tid < 8) {
        float v = red[tid];
#pragma unroll
        for (int m = 4; m; m >>= 1) v += __shfl_xor_sync(0xffu, v, m);
        if (tid == 0) red[0] = rsqrtf(v * (1.0f / DIM) + 1e-6f);
    }
    __syncthreads();
    float scale = red[0];

    for (int p = tid; p < NH * NPAIR; p += 256) {
        int head = p >> 6, j = p & 63;
        int i0 = head * HD + 2 * j;
        float2 v = *(const float2*)&xp[i0];
        float2 gv = *(const float2*)&g[i0];
        float xr = v.x * scale * gv.x;
        float xi = v.y * scale * gv.y;
        float c = g_cos[row * NPAIR + j];
        float s = g_sin[row * NPAIR + j];
        float yr = (xr * c - xi * s) * outscale;
        float yi = (xr * s + xi * c) * outscale;
        if (which == 0) {
            __half hr = __float2half(yr);
            __half hi2 = __float2half(yi);
            __half lr = __float2half(yr - __half2float(hr));
            __half li = __float2half(yi - __half2float(hi2));
            *(__half2*)&qh[(size_t)row * DIM + i0] = {hr, hi2};
            *(__half2*)&ql[(size_t)row * DIM + i0] = {lr, li};
        } else {
            *(__half2*)&kh[(size_t)row * DIM + i0] = {__float2half(yr), __float2half(yi)};
        }
    }
}

// ---------------- persistent fp16 flash attention (delayed PV) --------------
#define ATT_Q    0
#define ATT_K    65536
#define ATT_V    98304
#define ATT_WS   147456
#define ATT_SMEM (147456 + 32)

__global__ __launch_bounds__(256, 1) void attention_hmma(
    const __half* __restrict__ Qh, const __half* __restrict__ Ql,
    const __half* __restrict__ Kh, const __half* __restrict__ Vh,
    __half* __restrict__ Oh, __half* __restrict__ Ol) {
    extern __shared__ char dsm[];
    uint32_t sbase = smem_u32(dsm);
    int* wslot = (int*)(dsm + ATT_WS);

    int tid = threadIdx.x, wid = tid >> 5, lane = tid & 31;

    int a_r = wid * 16 + (lane & 7) + ((lane >> 3) & 1) * 8;
    int a_half = lane >> 4;
    int b_r = ((lane >> 4) & 1) * 8 + (lane & 7);
    int b_half = (lane >> 3) & 1;
    int v_r = (lane & 15);
    int vg = (lane >> 4);

    for (;;) {
        if (tid == 0) wslot[0] = atomicAdd(&g_work[1], 1);
        __syncthreads();
        int item = wslot[0];
        if (item >= N_ITEM) return;
        int qb = N_QB - 1 - item / NH;
        int h = item % NH;
        int q0 = qb * 128;

        {
            const __half* gq[2] = {Qh, Ql};
#pragma unroll
            for (int op = 0; op < 2; op++) {
                const __half* src = gq[op] + (size_t)q0 * DIM + h * HD;
                uint32_t dst = sbase + ATT_Q + (uint32_t)op * 32768;
#pragma unroll
                for (int it = 0; it < 8; it++) {
                    int idx = it * 256 + tid;
                    int r = idx >> 4, gg = idx & 15;
                    uint32_t off = (uint32_t)((gg >> 3) * 16384) + SWZ128((uint32_t)(r * 128 + (gg & 7) * 16));
                    CP_ASYNC16(dst + off, src + (size_t)r * DIM + gg * 8);
                }
            }
            CP_COMMIT();
        }

        auto load_kv = [&](int t) {
            int k0 = t * 64;
            uint32_t kdst = sbase + ATT_K + (uint32_t)(t & 1) * 16384;
            uint32_t vdst = sbase + ATT_V + (uint32_t)(t % 3) * 16384;
            const __half* ksrc = Kh + (size_t)k0 * DIM + h * HD;
            const __half* vsrc = Vh + (size_t)k0 * DIM + h * HD;
#pragma unroll
            for (int it = 0; it < 4; it++) {
                int idx = it * 256 + tid;
                int r = idx >> 4, gg = idx & 15;
                uint32_t off = (uint32_t)((gg >> 3) * 8192) + SWZ128((uint32_t)(r * 128 + (gg & 7) * 16));
                CP_ASYNC16(kdst + off, ksrc + (size_t)r * DIM + gg * 8);
                CP_ASYNC16(vdst + off, vsrc + (size_t)r * DIM + gg * 8);
            }
        };

        float O[16][4];
#pragma unroll
        for (int i = 0; i < 16; i++)
#pragma unroll
            for (int j = 0; j < 4; j++) O[i][j] = 0.f;
        float m0 = -1e30f, m1 = -1e30f, l0 = 0.f, l1 = 0.f;
        uint32_t PhP[4][4], PlP[4][4];

        int r0g = q0 + wid * 16 + (lane >> 2);
        int fr0 = r0g / FRAME, fr1 = (r0g + 8) / FRAME;
        int blkmin_f = q0 / FRAME;
        int fqmax = (q0 + 127) / FRAME;
        int ntile = ((fqmax + 1) * FRAME + 63) >> 6;

        load_kv(0); CP_COMMIT();
        load_kv(1); CP_COMMIT();

        for (int t = 0; t < ntile; t++) {
            if (t == ntile - 1) CP_WAIT0(); else CP_WAIT1();
            __syncthreads();

            int k0 = t * 64;
            uint32_t bKh = sbase + ATT_K + (uint32_t)(t & 1) * 16384;

            float S[8][4];
#pragma unroll
            for (int i = 0; i < 8; i++)
#pragma unroll
                for (int j = 0; j < 4; j++) S[i][j] = 0.f;

#pragma unroll
            for (int ks = 0; ks < 8; ks++) {
                uint32_t qa[4], ql4[4], kh4[16];
                uint32_t gq16 = (uint32_t)(((ks & 3) * 2 + a_half) * 16);
                uint32_t aoff = (uint32_t)((ks >> 2) * 16384) + SWZ128((uint32_t)(a_r * 128) + gq16);
                ldsm4(qa, sbase + ATT_Q + aoff);
                ldsm4(ql4, sbase + ATT_Q + 32768 + aoff);
                uint32_t gk16 = (uint32_t)(((ks & 3) * 2 + b_half) * 16);
#pragma unroll
                for (int nb = 0; nb < 4; nb++) {
                    uint32_t boff = (uint32_t)((ks >> 2) * 8192) +
                                    SWZ128((uint32_t)((nb * 16 + b_r) * 128) + gk16);
                    ldsm4(&kh4[nb * 4], bKh + boff);
                }
#pragma unroll
                for (int nf = 0; nf < 8; nf++) mma16816(S[nf], qa, &kh4[nf * 2]);
#pragma unroll
                for (int nf = 0; nf < 8; nf++) mma16816(S[nf], ql4, &kh4[nf * 2]);
            }

            if (t > 0) {
                uint32_t bVh = sbase + ATT_V + (uint32_t)((t - 1) % 3) * 16384;
#pragma unroll
                for (int j = 0; j < 4; j++) {
#pragma unroll
                    for (int dp = 0; dp < 4; dp++) {
                        int db0 = 2 * dp, db1 = 2 * dp + 1;
                        uint32_t row = (uint32_t)((j * 16 + v_r) * 128);
                        uint32_t voff0 = (uint32_t)((db0 >> 2) * 8192) +
                                         SWZ128(row + (uint32_t)(((db0 & 3) * 2 + vg) * 16));
                        uint32_t voff1 = (uint32_t)((db1 >> 2) * 8192) +
                                         SWZ128(row + (uint32_t)(((db1 & 3) * 2 + vg) * 16));
                        uint32_t vh_a[4], vh_b[4];
                        ldsm4t(vh_a, bVh + voff0);
                        ldsm4t(vh_b, bVh + voff1);
                        float* o0 = O[4 * dp + 0];
                        float* o1 = O[4 * dp + 1];
                        float* o2 = O[4 * dp + 2];
                        float* o3 = O[4 * dp + 3];
                        mma16816(o0, PhP[j], &vh_a[0]);
                        mma16816(o1, PhP[j], &vh_a[2]);
                        mma16816(o2, PhP[j], &vh_b[0]);
                        mma16816(o3, PhP[j], &vh_b[2]);
                        mma16816(o0, PlP[j], &vh_a[0]);
                        mma16816(o1, PlP[j], &vh_a[2]);
                        mma16816(o2, PlP[j], &vh_b[0]);
                        mma16816(o3, PlP[j], &vh_b[2]);
                    }
                }
            }

            if ((k0 + 63) / FRAME > blkmin_f) {
#pragma unroll
                for (int nf = 0; nf < 8; nf++) {
                    int c = k0 + nf * 8 + 2 * (lane & 3);
                    int cf0 = c / FRAME, cf1 = (c + 1) / FRAME;
                    if (cf0 > fr0) S[nf][0] = -1e30f;
                    if (cf1 > fr0) S[nf][1] = -1e30f;
                    if (cf0 > fr1) S[nf][2] = -1e30f;
                    if (cf1 > fr1) S[nf][3] = -1e30f;
                }
            }

            float mx0 = -1e30f, mx1 = -1e30f;
#pragma unroll
            for (int nf = 0; nf < 8; nf++) {
                mx0 = fmaxf(mx0, fmaxf(S[nf][0], S[nf][1]));
                mx1 = fmaxf(mx1, fmaxf(S[nf][2], S[nf][3]));
            }
            mx0 = fmaxf(mx0, __shfl_xor_sync(0xffffffffu, mx0, 1));
            mx0 = fmaxf(mx0, __shfl_xor_sync(0xffffffffu, mx0, 2));
            mx1 = fmaxf(mx1, __shfl_xor_sync(0xffffffffu, mx1, 1));
            mx1 = fmaxf(mx1, __shfl_xor_sync(0xffffffffu, mx1, 2));
            float mn0 = fmaxf(m0, mx0), mn1 = fmaxf(m1, mx1);
            float al0 = __expf(m0 - mn0), al1 = __expf(m1 - mn1);
            m0 = mn0; m1 = mn1;
#pragma unroll
            for (int i = 0; i < 16; i++) {
                O[i][0] *= al0; O[i][1] *= al0;
                O[i][2] *= al1; O[i][3] *= al1;
            }

            float ps0 = 0.f, ps1 = 0.f;
#pragma unroll
            for (int j = 0; j < 4; j++) {
                float p00 = __expf(S[2 * j][0] - mn0);
                float p01 = __expf(S[2 * j][1] - mn0);
                float p02 = __expf(S[2 * j][2] - mn1);
                float p03 = __expf(S[2 * j][3] - mn1);
                float p10 = __expf(S[2 * j + 1][0] - mn0);
                float p11 = __expf(S[2 * j + 1][1] - mn0);
                float p12 = __expf(S[2 * j + 1][2] - mn1);
                float p13 = __expf(S[2 * j + 1][3] - mn1);
                ps0 += (p00 + p01) + (p10 + p11);
                ps1 += (p02 + p03) + (p12 + p13);
                PhP[j][0] = pack_f16(p00, p01);
                PhP[j][1] = pack_f16(p02, p03);
                PhP[j][2] = pack_f16(p10, p11);
                PhP[j][3] = pack_f16(p12, p13);
                __half2 h0 = *(__half2*)&PhP[j][0];
                __half2 h1 = *(__half2*)&PhP[j][1];
                __half2 h2 = *(__half2*)&PhP[j][2];
                __half2 h3 = *(__half2*)&PhP[j][3];
                PlP[j][0] = pack_f16(p00 - __half2float(h0.x), p01 - __half2float(h0.y));
                PlP[j][1] = pack_f16(p02 - __half2float(h1.x), p03 - __half2float(h1.y));
                PlP[j][2] = pack_f16(p10 - __half2float(h2.x), p11 - __half2float(h2.y));
                PlP[j][3] = pack_f16(p12 - __half2float(h3.x), p13 - __half2float(h3.y));
            }
            ps0 += __shfl_xor_sync(0xffffffffu, ps0, 1);
            ps0 += __shfl_xor_sync(0xffffffffu, ps0, 2);
            ps1 += __shfl_xor_sync(0xffffffffu, ps1, 1);
            ps1 += __shfl_xor_sync(0xffffffffu, ps1, 2);
            l0 = l0 * al0 + ps0;
            l1 = l1 * al1 + ps1;

            __syncthreads();
            if (t + 2 < ntile) { load_kv(t + 2); CP_COMMIT(); }
        }

        {
            uint32_t bVh = sbase + ATT_V + (uint32_t)((ntile - 1) % 3) * 16384;
#pragma unroll
            for (int j = 0; j < 4; j++) {
#pragma unroll
                for (int dp = 0; dp < 4; dp++) {
                    int db0 = 2 * dp, db1 = 2 * dp + 1;
                    uint32_t row = (uint32_t)((j * 16 + v_r) * 128);
                    uint32_t voff0 = (uint32_t)((db0 >> 2) * 8192) +
                                     SWZ128(row + (uint32_t)(((db0 & 3) * 2 + vg) * 16));
                    uint32_t voff1 = (uint32_t)((db1 >> 2) * 8192) +
                                     SWZ128(row + (uint32_t)(((db1 & 3) * 2 + vg) * 16));
                    uint32_t vh_a[4], vh_b[4];
                    ldsm4t(vh_a, bVh + voff0);
                    ldsm4t(vh_b, bVh + voff1);
                    float* o0 = O[4 * dp + 0];
                    float* o1 = O[4 * dp + 1];
                    float* o2 = O[4 * dp + 2];
                    float* o3 = O[4 * dp + 3];
                    mma16816(o0, PhP[j], &vh_a[0]);
                    mma16816(o1, PhP[j], &vh_a[2]);
                    mma16816(o2, PhP[j], &vh_b[0]);
                    mma16816(o3, PhP[j], &vh_b[2]);
                    mma16816(o0, PlP[j], &vh_a[0]);
                    mma16816(o1, PlP[j], &vh_a[2]);
                    mma16816(o2, PlP[j], &vh_b[0]);
                    mma16816(o3, PlP[j], &vh_b[2]);
                }
            }
        }

        float inv0 = 1.0f / l0, inv1 = 1.0f / l1;
        int row0 = q0 + wid * 16 + (lane >> 2);
#pragma unroll
        for (int nf = 0; nf < 16; nf++) {
            int col = h * HD + nf * 8 + 2 * (lane & 3);
            float o00 = O[nf][0] * inv0, o01 = O[nf][1] * inv0;
            float o10 = O[nf][2] * inv1, o11 = O[nf][3] * inv1;
            uint32_t h0 = pack_f16(o00, o01);
            uint32_t h1 = pack_f16(o10, o11);
            __half2 hh0 = *(__half2*)&h0;
            __half2 hh1 = *(__half2*)&h1;
            uint32_t lo0 = pack_f16(o00 - __half2float(hh0.x), o01 - __half2float(hh0.y));
            uint32_t lo1 = pack_f16(o10 - __half2float(hh1.x), o11 - __half2float(hh1.y));
            *(uint32_t*)&Oh[(size_t)row0 * DIM + col] = h0;
            *(uint32_t*)&Ol[(size_t)row0 * DIM + col] = lo0;
            *(uint32_t*)&Oh[(size_t)(row0 + 8) * DIM + col] = h1;
            *(uint32_t*)&Ol[(size_t)(row0 + 8) * DIM + col] = lo1;
        }
    }
}

// ---------------- launch ----------------
extern "C" void kernel_launch(void* const* d_in, const int* in_sizes, int n_in,
                              void* d_out, int out_size) {
    const float* x  = (const float*)d_in[0];
    const float* Wq = (const float*)d_in[1];
    const float* bq = (const float*)d_in[2];
    const float* Wk = (const float*)d_in[3];
    const float* bk = (const float*)d_in[4];
    const float* Wv = (const float*)d_in[5];
    const float* bv = (const float*)d_in[6];
    const float* Wo = (const float*)d_in[7];
    const float* bo = (const float*)d_in[8];
    const float* gq = (const float*)d_in[9];
    const float* gk = (const float*)d_in[10];
    const float* ff = (const float*)d_in[11];
    const float* fh = (const float*)d_in[12];
    const float* fw = (const float*)d_in[13];
    float* out = (float*)d_out;

    float *qp, *kp;
    __half *ah, *al, *qh, *ql, *kh, *vh, *whb;
    int* workp;
    cudaGetSymbolAddress((void**)&qp, g_q);
    cudaGetSymbolAddress((void**)&kp, g_k);
    cudaGetSymbolAddress((void**)&ah, g_ah);
    cudaGetSymbolAddress((void**)&al, g_al);
    cudaGetSymbolAddress((void**)&whb, g_wh);
    cudaGetSymbolAddress((void**)&qh, g_qh);
    cudaGetSymbolAddress((void**)&ql, g_ql);
    cudaGetSymbolAddress((void**)&kh, g_kh);
    cudaGetSymbolAddress((void**)&vh, g_vh);
    cudaGetSymbolAddress((void**)&workp, g_work);

    cudaFuncSetAttribute(gemm_hmma,
                         cudaFuncAttributeMaxDynamicSharedMemorySize, GSMEM);
    cudaFuncSetAttribute(attention_hmma,
                         cudaFuncAttributeMaxDynamicSharedMemorySize, ATT_SMEM);

    cudaMemsetAsync(workp, 0, 4 * sizeof(int));

    angles_kernel<<<(L_TOK * NPAIR + 255) / 256, 256>>>(ff, fh, fw);

    const int NELT = L_TOK * DIM;
    split_kernel<<<(NELT / 4 + 255) / 256, 256>>>(x, ah, al, NELT);

    transpose_half4_kernel<<<dim3(DIM / 32, DIM / 32, 4), dim3(32, 8)>>>(
        Wq, Wk, Wv, Wo, whb);

    const size_t WSZ = (size_t)DIM * DIM;
    GemmArgs ga;
    ga.wh0 = whb;           ga.b0 = bq; ga.o0 = qp;
    ga.wh1 = whb + WSZ;     ga.b1 = bk; ga.o1 = kp;
    ga.wh2 = whb + 2 * WSZ; ga.b2 = bv;
    ga.ovh = vh;
    gemm_hmma<<<148, 256, GSMEM>>>(ah, al, ga, 1080, 1, workp + 0);

    rmsnorm_rope_split2<<<dim3(L_TOK, 2), 256>>>(qp, kp, gq, gk, qh, ql, kh);

    attention_hmma<<<148, 256, ATT_SMEM>>>(qh, ql, kh, vh, ah, al);

    GemmArgs go;
    go.wh0 = whb + 3 * WSZ; go.b0 = bo; go.o0 = out;
    go.wh1 = go.wh0; go.b1 = bo; go.o1 = out;
    go.wh2 = go.wh0; go.b2 = bo;
    go.ovh = vh;
    gemm_hmma<<<148, 256, GSMEM>>>(ah, al, go, 360, 0, workp + 2);
}

// round 14
// speedup vs baseline: 1.0544x; 1.0544x over previous
#include <cuda_runtime.h>
#include <cuda_fp16.h>
#include <math.h>
#include <stdint.h>

#define L_TOK 3840
#define DIM   1536
#define NH    12
#define HD    128
#define FRAME 480
#define NPAIR 64
#define N_QB  30
#define N_ITEM (N_QB * NH)

// ---------------- device scratch (no allocs allowed) ----------------
__device__ float g_q[L_TOK * DIM];
__device__ float g_k[L_TOK * DIM];
__device__ float g_cos[L_TOK * NPAIR];
__device__ float g_sin[L_TOK * NPAIR];
__device__ int   g_work[4];
__device__ __half g_ah[L_TOK * DIM];      // A hi (x, later attn out)
__device__ __half g_al[L_TOK * DIM];      // A lo
__device__ __half g_wh[4][DIM * DIM];     // W^T fp16 (single) for q,k,v,o
__device__ __half g_qh[L_TOK * DIM];
__device__ __half g_ql[L_TOK * DIM];
__device__ __half g_kh[L_TOK * DIM];      // K single fp16
__device__ __half g_vh[L_TOK * DIM];      // V single fp16

// =================== sm_80-era PTX helpers (valid on plain sm_103) ==========
__device__ __forceinline__ uint32_t smem_u32(const void* p) {
    uint32_t a;
    asm("{ .reg .u64 t; cvta.to.shared.u64 t, %1; cvt.u32.u64 %0, t; }" : "=r"(a) : "l"(p));
    return a;
}
#define CP_ASYNC16(dst, src) \
    asm volatile("cp.async.cg.shared.global [%0], [%1], 16;" :: "r"(dst), "l"(src))
#define CP_COMMIT() asm volatile("cp.async.commit_group;" ::: "memory")
#define CP_WAIT1()  asm volatile("cp.async.wait_group 1;" ::: "memory")
#define CP_WAIT0()  asm volatile("cp.async.wait_group 0;" ::: "memory")

__device__ __forceinline__ void ldsm4(uint32_t* r, uint32_t addr) {
    asm volatile("ldmatrix.sync.aligned.m8n8.x4.shared.b16 {%0,%1,%2,%3}, [%4];"
                 : "=r"(r[0]), "=r"(r[1]), "=r"(r[2]), "=r"(r[3]) : "r"(addr));
}
__device__ __forceinline__ void ldsm4t(uint32_t* r, uint32_t addr) {
    asm volatile("ldmatrix.sync.aligned.m8n8.x4.trans.shared.b16 {%0,%1,%2,%3}, [%4];"
                 : "=r"(r[0]), "=r"(r[1]), "=r"(r[2]), "=r"(r[3]) : "r"(addr));
}
__device__ __forceinline__ void mma16816(float* c, const uint32_t* a, const uint32_t* b) {
    asm volatile("mma.sync.aligned.m16n8k16.row.col.f32.f16.f16.f32 "
                 "{%0,%1,%2,%3}, {%4,%5,%6,%7}, {%8,%9}, {%0,%1,%2,%3};"
                 : "+f"(c[0]), "+f"(c[1]), "+f"(c[2]), "+f"(c[3])
                 : "r"(a[0]), "r"(a[1]), "r"(a[2]), "r"(a[3]), "r"(b[0]), "r"(b[1]));
}
#define SWZ128(off) ((off) ^ (((off) >> 3) & 0x70))

__device__ __forceinline__ uint32_t pack_f16(float lo, float hi) {
    uint32_t r;
    asm("cvt.rn.f16x2.f32 %0, %1, %2;" : "=r"(r) : "f"(hi), "f"(lo));
    return r;
}

// ---------------- angle table ----------------
__global__ void angles_kernel(const float* __restrict__ ff,
                              const float* __restrict__ fh,
                              const float* __restrict__ fw) {
    int idx = blockIdx.x * blockDim.x + threadIdx.x;
    if (idx >= L_TOK * NPAIR) return;
    int l = idx / NPAIR, j = idx % NPAIR;
    int f = l / FRAME, r = l % FRAME;
    int h = r / 30, w = r % 30;
    float a;
    if (j < 22)      a = ff[f * 22 + j];
    else if (j < 43) a = fh[h * 21 + (j - 22)];
    else             a = fw[w * 21 + (j - 43)];
    g_cos[idx] = cosf(a);
    g_sin[idx] = sinf(a);
}

// ---------------- split fp32 -> fp16 hi/lo ----------------
__global__ __launch_bounds__(256) void split_kernel(const float* __restrict__ x,
                                                    __half* __restrict__ hi,
                                                    __half* __restrict__ lo, int n) {
    int i = blockIdx.x * blockDim.x + threadIdx.x;
    if (i * 4 >= n) return;
    float4 v = *(const float4*)&x[i * 4];
    __half h0 = __float2half(v.x), h1 = __float2half(v.y);
    __half h2 = __float2half(v.z), h3 = __float2half(v.w);
    __half l0 = __float2half(v.x - __half2float(h0));
    __half l1 = __float2half(v.y - __half2float(h1));
    __half l2 = __float2half(v.z - __half2float(h2));
    __half l3 = __float2half(v.w - __half2float(h3));
    __half2* ph = (__half2*)&hi[i * 4];
    __half2* pl = (__half2*)&lo[i * 4];
    ph[0] = {h0, h1}; ph[1] = {h2, h3};
    pl[0] = {l0, l1}; pl[1] = {l2, l3};
}

// ------- fused transpose of 4 weights [K,N] -> [N,K], single fp16 -------
__global__ __launch_bounds__(256) void transpose_half4_kernel(
    const float* __restrict__ W0, const float* __restrict__ W1,
    const float* __restrict__ W2, const float* __restrict__ W3,
    __half* __restrict__ ThBase) {
    __shared__ float t[32][33];
    int z = blockIdx.z;
    const float* W = (z == 0) ? W0 : (z == 1) ? W1 : (z == 2) ? W2 : W3;
    __half* Th = ThBase + (size_t)z * DIM * DIM;
    int tx = threadIdx.x, ty = threadIdx.y;  // 32 x 8
    int x0 = blockIdx.x * 32, y0 = blockIdx.y * 32;
#pragma unroll
    for (int i = 0; i < 32; i += 8)
        t[ty + i][tx] = W[(size_t)(y0 + ty + i) * DIM + x0 + tx];
    __syncthreads();
#pragma unroll
    for (int i = 0; i < 32; i += 8)
        Th[(size_t)(x0 + ty + i) * DIM + y0 + tx] = __float2half(t[tx][ty + i]);
}

// ------- HMMA fp16 2-term GEMM: BK=64, 256t, 2 CTAs/SM for 4 warps/SMSP -----
#define GK       64
#define TILE_B   16384
#define BUF_B    (3 * TILE_B)     // Ah, Al, Bh
#define GSMEM    (1024 + 2 * BUF_B)   // 99328 B -> 2 CTAs/SM

struct GemmArgs {
    const __half *wh0, *wh1, *wh2;
    const float *b0, *b1, *b2;
    float *o0, *o1;
    __half *ovh;
};

__global__ __launch_bounds__(256, 2) void gemm_hmma(const __half* __restrict__ Ah,
                                                    const __half* __restrict__ Al,
                                                    GemmArgs ga) {
    extern __shared__ char dsm[];
    uint32_t raw = smem_u32(dsm);
    uint32_t sbase = (raw + 1023u) & ~1023u;

    int tid = threadIdx.x;
    int wid = tid >> 5, lane = tid & 31;
    int m0 = blockIdx.y * 128;
    int n0 = blockIdx.x * 128;

    const __half* Bh;
    const float* bias;
    float* Cf;
    if (blockIdx.z == 0)      { Bh = ga.wh0; bias = ga.b0; Cf = ga.o0; }
    else if (blockIdx.z == 1) { Bh = ga.wh1; bias = ga.b1; Cf = ga.o1; }
    else                      { Bh = ga.wh2; bias = ga.b2; Cf = nullptr; }

    const __half* srcs[3] = {Ah, Al, Bh};
    const int rbase[3] = {m0, m0, n0};

    auto load_chunk = [&](int c, int buf) {
        uint32_t dst0 = sbase + (uint32_t)buf * BUF_B;
#pragma unroll
        for (int it = 0; it < 12; it++) {
            int idx = it * 256 + tid;
            int tile = idx >> 10;
            int rem = idx & 1023;
            int r = rem >> 3, g = rem & 7;
            const __half* src = srcs[tile] + (size_t)(rbase[tile] + r) * DIM + c * GK + g * 8;
            uint32_t off = (uint32_t)(r * 128 + g * 16);
            CP_ASYNC16(dst0 + (uint32_t)tile * TILE_B + SWZ128(off), src);
        }
    };

    float Creg[2][8][4];
#pragma unroll
    for (int mt = 0; mt < 2; mt++)
#pragma unroll
        for (int nf = 0; nf < 8; nf++)
#pragma unroll
            for (int j = 0; j < 4; j++) Creg[mt][nf][j] = 0.f;

    int m_base = (wid & 3) * 32;
    int n_base = (wid >> 2) * 64;
    int a_r = m_base + (lane & 7) + ((lane >> 3) & 1) * 8;
    int a_g = (lane >> 4);
    int b_r = n_base + ((lane >> 4) & 1) * 8 + (lane & 7);
    int b_g = (lane >> 3) & 1;

    const int NCH = DIM / GK;  // 24
    load_chunk(0, 0); CP_COMMIT();
    load_chunk(1, 1); CP_COMMIT();

    for (int c = 0; c < NCH; c++) {
        if (c == NCH - 1) CP_WAIT0(); else CP_WAIT1();
        __syncthreads();

        int buf = c & 1;
        uint32_t sb = sbase + (uint32_t)buf * BUF_B;
        uint32_t sAh = sb, sAl = sb + TILE_B, sBh = sb + 2 * TILE_B;

#pragma unroll
        for (int ks = 0; ks < 4; ks++) {
            uint32_t ah[2][4], al[2][4];
#pragma unroll
            for (int mt = 0; mt < 2; mt++) {
                uint32_t off = SWZ128((uint32_t)((a_r + mt * 16) * 128 + ((a_g + 2 * ks) * 16)));
                ldsm4(ah[mt], sAh + off);
                ldsm4(al[mt], sAl + off);
            }
            // B fragments in two groups of 8 regs to cap live registers
#pragma unroll
            for (int grp = 0; grp < 2; grp++) {
                uint32_t bh[8];
#pragma unroll
                for (int half = 0; half < 2; half++) {
                    int nf2 = grp * 2 + half;
                    uint32_t off = SWZ128((uint32_t)((b_r + nf2 * 16) * 128 + ((b_g + 2 * ks) * 16)));
                    ldsm4(&bh[half * 4], sBh + off);
                }
#pragma unroll
                for (int nfl = 0; nfl < 4; nfl++)
#pragma unroll
                    for (int mt = 0; mt < 2; mt++)
                        mma16816(Creg[mt][grp * 4 + nfl], ah[mt], &bh[nfl * 2]);
#pragma unroll
                for (int nfl = 0; nfl < 4; nfl++)
#pragma unroll
                    for (int mt = 0; mt < 2; mt++)
                        mma16816(Creg[mt][grp * 4 + nfl], al[mt], &bh[nfl * 2]);
            }
        }
        __syncthreads();
        if (c + 2 < NCH) { load_chunk(c + 2, buf); CP_COMMIT(); }
    }

#pragma unroll
    for (int mt = 0; mt < 2; mt++) {
#pragma unroll
        for (int nf = 0; nf < 8; nf++) {
            int r0 = m0 + m_base + mt * 16 + (lane >> 2);
            int col = n0 + n_base + nf * 8 + (lane & 3) * 2;
            float2 bv = *(const float2*)&bias[col];
            float* cc = Creg[mt][nf];
            float c00 = cc[0] + bv.x, c01 = cc[1] + bv.y;
            float c10 = cc[2] + bv.x, c11 = cc[3] + bv.y;
            if (Cf == nullptr) {
                *(uint32_t*)&ga.ovh[(size_t)r0 * DIM + col] = pack_f16(c00, c01);
                *(uint32_t*)&ga.ovh[(size_t)(r0 + 8) * DIM + col] = pack_f16(c10, c11);
            } else {
                *(float2*)&Cf[(size_t)r0 * DIM + col] = {c00, c01};
                *(float2*)&Cf[(size_t)(r0 + 8) * DIM + col] = {c10, c11};
            }
        }
    }
}

// ---------------- fused RMSNorm + RoPE: q -> fp16 hi/lo, k -> fp16 single ---
__global__ __launch_bounds__(256) void rmsnorm_rope_split2(
    const float* __restrict__ xq, const float* __restrict__ xk,
    const float* __restrict__ gqv, const float* __restrict__ gkv,
    __half* __restrict__ qh, __half* __restrict__ ql,
    __half* __restrict__ kh) {
    int row = blockIdx.x;
    int which = blockIdx.y;
    const float* xp = (which ? xk : xq) + (size_t)row * DIM;
    const float* g = which ? gkv : gqv;
    float outscale = which ? 1.0f : 0.08838834764831845f;
    int tid = threadIdx.x;

    float ss = 0.f;
    for (int i = tid; i < DIM; i += 256) {
        float v = xp[i];
        ss += v * v;
    }
    __shared__ float red[8];
#pragma unroll
    for (int m = 16; m; m >>= 1) ss += __shfl_xor_sync(0xffffffffu, ss, m);
    if ((tid & 31) == 0) red[tid >> 5] = ss;
    __syncthreads();
    if (tid < 8) {
        float v = red[tid];
#pragma unroll
        for (int m = 4; m; m >>= 1) v += __shfl_xor_sync(0xffu, v, m);
        if (tid == 0) red[0] = rsqrtf(v * (1.0f / DIM) + 1e-6f);
    }
    __syncthreads();
    float scale = red[0];

    for (int p = tid; p < NH * NPAIR; p += 256) {
        int head = p >> 6, j = p & 63;
        int i0 = head * HD + 2 * j;
        float2 v = *(const float2*)&xp[i0];
        float2 gv = *(const float2*)&g[i0];
        float xr = v.x * scale * gv.x;
        float xi = v.y * scale * gv.y;
        float c = g_cos[row * NPAIR + j];
        float s = g_sin[row * NPAIR + j];
        float yr = (xr * c - xi * s) * outscale;
        float yi = (xr * s + xi * c) * outscale;
        if (which == 0) {
            __half hr = __float2half(yr);
            __half hi2 = __float2half(yi);
            __half lr = __float2half(yr - __half2float(hr));
            __half li = __float2half(yi - __half2float(hi2));
            *(__half2*)&qh[(size_t)row * DIM + i0] = {hr, hi2};
            *(__half2*)&ql[(size_t)row * DIM + i0] = {lr, li};
        } else {
            *(__half2*)&kh[(size_t)row * DIM + i0] = {__float2half(yr), __float2half(yi)};
        }
    }
}

// ---------------- persistent fp16 flash attention (delayed PV) --------------
#define ATT_Q    0
#define ATT_K    65536
#define ATT_V    98304
#define ATT_WS   147456
#define ATT_SMEM (147456 + 32)

__global__ __launch_bounds__(256, 1) void attention_hmma(
    const __half* __restrict__ Qh, const __half* __restrict__ Ql,
    const __half* __restrict__ Kh, const __half* __restrict__ Vh,
    __half* __restrict__ Oh, __half* __restrict__ Ol) {
    extern __shared__ char dsm[];
    uint32_t sbase = smem_u32(dsm);
    int* wslot = (int*)(dsm + ATT_WS);

    int tid = threadIdx.x, wid = tid >> 5, lane = tid & 31;

    int a_r = wid * 16 + (lane & 7) + ((lane >> 3) & 1) * 8;
    int a_half = lane >> 4;
    int b_r = ((lane >> 4) & 1) * 8 + (lane & 7);
    int b_half = (lane >> 3) & 1;
    int v_r = (lane & 15);
    int vg = (lane >> 4);

    for (;;) {
        if (tid == 0) wslot[0] = atomicAdd(&g_work[1], 1);
        __syncthreads();
        int item = wslot[0];
        if (item >= N_ITEM) return;
        int qb = N_QB - 1 - item / NH;
        int h = item % NH;
        int q0 = qb * 128;

        {
            const __half* gq[2] = {Qh, Ql};
#pragma unroll
            for (int op = 0; op < 2; op++) {
                const __half* src = gq[op] + (size_t)q0 * DIM + h * HD;
                uint32_t dst = sbase + ATT_Q + (uint32_t)op * 32768;
#pragma unroll
                for (int it = 0; it < 8; it++) {
                    int idx = it * 256 + tid;
                    int r = idx >> 4, gg = idx & 15;
                    uint32_t off = (uint32_t)((gg >> 3) * 16384) + SWZ128((uint32_t)(r * 128 + (gg & 7) * 16));
                    CP_ASYNC16(dst + off, src + (size_t)r * DIM + gg * 8);
                }
            }
            CP_COMMIT();
        }

        auto load_kv = [&](int t) {
            int k0 = t * 64;
            uint32_t kdst = sbase + ATT_K + (uint32_t)(t & 1) * 16384;
            uint32_t vdst = sbase + ATT_V + (uint32_t)(t % 3) * 16384;
            const __half* ksrc = Kh + (size_t)k0 * DIM + h * HD;
            const __half* vsrc = Vh + (size_t)k0 * DIM + h * HD;
#pragma unroll
            for (int it = 0; it < 4; it++) {
                int idx = it * 256 + tid;
                int r = idx >> 4, gg = idx & 15;
                uint32_t off = (uint32_t)((gg >> 3) * 8192) + SWZ128((uint32_t)(r * 128 + (gg & 7) * 16));
                CP_ASYNC16(kdst + off, ksrc + (size_t)r * DIM + gg * 8);
                CP_ASYNC16(vdst + off, vsrc + (size_t)r * DIM + gg * 8);
            }
        };

        float O[16][4];
#pragma unroll
        for (int i = 0; i < 16; i++)
#pragma unroll
            for (int j = 0; j < 4; j++) O[i][j] = 0.f;
        float m0 = -1e30f, m1 = -1e30f, l0 = 0.f, l1 = 0.f;
        uint32_t PhP[4][4], PlP[4][4];

        int r0g = q0 + wid * 16 + (lane >> 2);
        int fr0 = r0g / FRAME, fr1 = (r0g + 8) / FRAME;
        int blkmin_f = q0 / FRAME;
        int fqmax = (q0 + 127) / FRAME;
        int ntile = ((fqmax + 1) * FRAME + 63) >> 6;

        load_kv(0); CP_COMMIT();
        load_kv(1); CP_COMMIT();

        for (int t = 0; t < ntile; t++) {
            if (t == ntile - 1) CP_WAIT0(); else CP_WAIT1();
            __syncthreads();

            int k0 = t * 64;
            uint32_t bKh = sbase + ATT_K + (uint32_t)(t & 1) * 16384;

            float S[8][4];
#pragma unroll
            for (int i = 0; i < 8; i++)
#pragma unroll
                for (int j = 0; j < 4; j++) S[i][j] = 0.f;

#pragma unroll
            for (int ks = 0; ks < 8; ks++) {
                uint32_t qa[4], ql4[4], kh4[16];
                uint32_t gq16 = (uint32_t)(((ks & 3) * 2 + a_half) * 16);
                uint32_t aoff = (uint32_t)((ks >> 2) * 16384) + SWZ128((uint32_t)(a_r * 128) + gq16);
                ldsm4(qa, sbase + ATT_Q + aoff);
                ldsm4(ql4, sbase + ATT_Q + 32768 + aoff);
                uint32_t gk16 = (uint32_t)(((ks & 3) * 2 + b_half) * 16);
#pragma unroll
                for (int nb = 0; nb < 4; nb++) {
                    uint32_t boff = (uint32_t)((ks >> 2) * 8192) +
                                    SWZ128((uint32_t)((nb * 16 + b_r) * 128) + gk16);
                    ldsm4(&kh4[nb * 4], bKh + boff);
                }
#pragma unroll
                for (int nf = 0; nf < 8; nf++) mma16816(S[nf], qa, &kh4[nf * 2]);
#pragma unroll
                for (int nf = 0; nf < 8; nf++) mma16816(S[nf], ql4, &kh4[nf * 2]);
            }

            if (t > 0) {
                uint32_t bVh = sbase + ATT_V + (uint32_t)((t - 1) % 3) * 16384;
#pragma unroll
                for (int j = 0; j < 4; j++) {
#pragma unroll
                    for (int dp = 0; dp < 4; dp++) {
                        int db0 = 2 * dp, db1 = 2 * dp + 1;
                        uint32_t row = (uint32_t)((j * 16 + v_r) * 128);
                        uint32_t voff0 = (uint32_t)((db0 >> 2) * 8192) +
                                         SWZ128(row + (uint32_t)(((db0 & 3) * 2 + vg) * 16));
                        uint32_t voff1 = (uint32_t)((db1 >> 2) * 8192) +
                                         SWZ128(row + (uint32_t)(((db1 & 3) * 2 + vg) * 16));
                        uint32_t vh_a[4], vh_b[4];
                        ldsm4t(vh_a, bVh + voff0);
                        ldsm4t(vh_b, bVh + voff1);
                        float* o0 = O[4 * dp + 0];
                        float* o1 = O[4 * dp + 1];
                        float* o2 = O[4 * dp + 2];
                        float* o3 = O[4 * dp + 3];
                        mma16816(o0, PhP[j], &vh_a[0]);
                        mma16816(o1, PhP[j], &vh_a[2]);
                        mma16816(o2, PhP[j], &vh_b[0]);
                        mma16816(o3, PhP[j], &vh_b[2]);
                        mma16816(o0, PlP[j], &vh_a[0]);
                        mma16816(o1, PlP[j], &vh_a[2]);
                        mma16816(o2, PlP[j], &vh_b[0]);
                        mma16816(o3, PlP[j], &vh_b[2]);
                    }
                }
            }

            if ((k0 + 63) / FRAME > blkmin_f) {
#pragma unroll
                for (int nf = 0; nf < 8; nf++) {
                    int c = k0 + nf * 8 + 2 * (lane & 3);
                    int cf0 = c / FRAME, cf1 = (c + 1) / FRAME;
                    if (cf0 > fr0) S[nf][0] = -1e30f;
                    if (cf1 > fr0) S[nf][1] = -1e30f;
                    if (cf0 > fr1) S[nf][2] = -1e30f;
                    if (cf1 > fr1) S[nf][3] = -1e30f;
                }
            }

            float mx0 = -1e30f, mx1 = -1e30f;
#pragma unroll
            for (int nf = 0; nf < 8; nf++) {
                mx0 = fmaxf(mx0, fmaxf(S[nf][0], S[nf][1]));
                mx1 = fmaxf(mx1, fmaxf(S[nf][2], S[nf][3]));
            }
            mx0 = fmaxf(mx0, __shfl_xor_sync(0xffffffffu, mx0, 1));
            mx0 = fmaxf(mx0, __shfl_xor_sync(0xffffffffu, mx0, 2));
            mx1 = fmaxf(mx1, __shfl_xor_sync(0xffffffffu, mx1, 1));
            mx1 = fmaxf(mx1, __shfl_xor_sync(0xffffffffu, mx1, 2));
            float mn0 = fmaxf(m0, mx0), mn1 = fmaxf(m1, mx1);
            float al0 = __expf(m0 - mn0), al1 = __expf(m1 - mn1);
            m0 = mn0; m1 = mn1;
#pragma unroll
            for (int i = 0; i < 16; i++) {
                O[i][0] *= al0; O[i][1] *= al0;
                O[i][2] *= al1; O[i][3] *= al1;
            }

            float ps0 = 0.f, ps1 = 0.f;
#pragma unroll
            for (int j = 0; j < 4; j++) {
                float p00 = __expf(S[2 * j][0] - mn0);
                float p01 = __expf(S[2 * j][1] - mn0);
                float p02 = __expf(S[2 * j][2] - mn1);
                float p03 = __expf(S[2 * j][3] - mn1);
                float p10 = __expf(S[2 * j + 1][0] - mn0);
                float p11 = __expf(S[2 * j + 1][1] - mn0);
                float p12 = __expf(S[2 * j + 1][2] - mn1);
                float p13 = __expf(S[2 * j + 1][3] - mn1);
                ps0 += (p00 + p01) + (p10 + p11);
                ps1 += (p02 + p03) + (p12 + p13);
                PhP[j][0] = pack_f16(p00, p01);
                PhP[j][1] = pack_f16(p02, p03);
                PhP[j][2] = pack_f16(p10, p11);
                PhP[j][3] = pack_f16(p12, p13);
                __half2 h0 = *(__half2*)&PhP[j][0];
                __half2 h1 = *(__half2*)&PhP[j][1];
                __half2 h2 = *(__half2*)&PhP[j][2];
                __half2 h3 = *(__half2*)&PhP[j][3];
                PlP[j][0] = pack_f16(p00 - __half2float(h0.x), p01 - __half2float(h0.y));
                PlP[j][1] = pack_f16(p02 - __half2float(h1.x), p03 - __half2float(h1.y));
                PlP[j][2] = pack_f16(p10 - __half2float(h2.x), p11 - __half2float(h2.y));
                PlP[j][3] = pack_f16(p12 - __half2float(h3.x), p13 - __half2float(h3.y));
            }
            ps0 += __shfl_xor_sync(0xffffffffu, ps0, 1);
            ps0 += __shfl_xor_sync(0xffffffffu, ps0, 2);
            ps1 += __shfl_xor_sync(0xffffffffu, ps1, 1);
            ps1 += __shfl_xor_sync(0xffffffffu, ps1, 2);
            l0 = l0 * al0 + ps0;
            l1 = l1 * al1 + ps1;

            __syncthreads();
            if (t + 2 < ntile) { load_kv(t + 2); CP_COMMIT(); }
        }

        {
            uint32_t bVh = sbase + ATT_V + (uint32_t)((ntile - 1) % 3) * 16384;
#pragma unroll
            for (int j = 0; j < 4; j++) {
#pragma unroll
                for (int dp = 0; dp < 4; dp++) {
                    int db0 = 2 * dp, db1 = 2 * dp + 1;
                    uint32_t row = (uint32_t)((j * 16 + v_r) * 128);
                    uint32_t voff0 = (uint32_t)((db0 >> 2) * 8192) +
                                     SWZ128(row + (uint32_t)(((db0 & 3) * 2 + vg) * 16));
                    uint32_t voff1 = (uint32_t)((db1 >> 2) * 8192) +
                                     SWZ128(row + (uint32_t)(((db1 & 3) * 2 + vg) * 16));
                    uint32_t vh_a[4], vh_b[4];
                    ldsm4t(vh_a, bVh + voff0);
                    ldsm4t(vh_b, bVh + voff1);
                    float* o0 = O[4 * dp + 0];
                    float* o1 = O[4 * dp + 1];
                    float* o2 = O[4 * dp + 2];
                    float* o3 = O[4 * dp + 3];
                    mma16816(o0, PhP[j], &vh_a[0]);
                    mma16816(o1, PhP[j], &vh_a[2]);
                    mma16816(o2, PhP[j], &vh_b[0]);
                    mma16816(o3, PhP[j], &vh_b[2]);
                    mma16816(o0, PlP[j], &vh_a[0]);
                    mma16816(o1, PlP[j], &vh_a[2]);
                    mma16816(o2, PlP[j], &vh_b[0]);
                    mma16816(o3, PlP[j], &vh_b[2]);
                }
            }
        }

        float inv0 = 1.0f / l0, inv1 = 1.0f / l1;
        int row0 = q0 + wid * 16 + (lane >> 2);
#pragma unroll
        for (int nf = 0; nf < 16; nf++) {
            int col = h * HD + nf * 8 + 2 * (lane & 3);
            float o00 = O[nf][0] * inv0, o01 = O[nf][1] * inv0;
            float o10 = O[nf][2] * inv1, o11 = O[nf][3] * inv1;
            uint32_t h0 = pack_f16(o00, o01);
            uint32_t h1 = pack_f16(o10, o11);
            __half2 hh0 = *(__half2*)&h0;
            __half2 hh1 = *(__half2*)&h1;
            uint32_t lo0 = pack_f16(o00 - __half2float(hh0.x), o01 - __half2float(hh0.y));
            uint32_t lo1 = pack_f16(o10 - __half2float(hh1.x), o11 - __half2float(hh1.y));
            *(uint32_t*)&Oh[(size_t)row0 * DIM + col] = h0;
            *(uint32_t*)&Ol[(size_t)row0 * DIM + col] = lo0;
            *(uint32_t*)&Oh[(size_t)(row0 + 8) * DIM + col] = h1;
            *(uint32_t*)&Ol[(size_t)(row0 + 8) * DIM + col] = lo1;
        }
    }
}

// ---------------- launch ----------------
extern "C" void kernel_launch(void* const* d_in, const int* in_sizes, int n_in,
                              void* d_out, int out_size) {
    const float* x  = (const float*)d_in[0];
    const float* Wq = (const float*)d_in[1];
    const float* bq = (const float*)d_in[2];
    const float* Wk = (const float*)d_in[3];
    const float* bk = (const float*)d_in[4];
    const float* Wv = (const float*)d_in[5];
    const float* bv = (const float*)d_in[6];
    const float* Wo = (const float*)d_in[7];
    const float* bo = (const float*)d_in[8];
    const float* gq = (const float*)d_in[9];
    const float* gk = (const float*)d_in[10];
    const float* ff = (const float*)d_in[11];
    const float* fh = (const float*)d_in[12];
    const float* fw = (const float*)d_in[13];
    float* out = (float*)d_out;

    float *qp, *kp;
    __half *ah, *al, *qh, *ql, *kh, *vh, *whb;
    int* workp;
    cudaGetSymbolAddress((void**)&qp, g_q);
    cudaGetSymbolAddress((void**)&kp, g_k);
    cudaGetSymbolAddress((void**)&ah, g_ah);
    cudaGetSymbolAddress((void**)&al, g_al);
    cudaGetSymbolAddress((void**)&whb, g_wh);
    cudaGetSymbolAddress((void**)&qh, g_qh);
    cudaGetSymbolAddress((void**)&ql, g_ql);
    cudaGetSymbolAddress((void**)&kh, g_kh);
    cudaGetSymbolAddress((void**)&vh, g_vh);
    cudaGetSymbolAddress((void**)&workp, g_work);

    cudaFuncSetAttribute(gemm_hmma,
                         cudaFuncAttributeMaxDynamicSharedMemorySize, GSMEM);
    cudaFuncSetAttribute(attention_hmma,
                         cudaFuncAttributeMaxDynamicSharedMemorySize, ATT_SMEM);

    cudaMemsetAsync(workp, 0, 4 * sizeof(int));

    angles_kernel<<<(L_TOK * NPAIR + 255) / 256, 256>>>(ff, fh, fw);

    const int NELT = L_TOK * DIM;
    split_kernel<<<(NELT / 4 + 255) / 256, 256>>>(x, ah, al, NELT);

    transpose_half4_kernel<<<dim3(DIM / 32, DIM / 32, 4), dim3(32, 8)>>>(
        Wq, Wk, Wv, Wo, whb);

    const size_t WSZ = (size_t)DIM * DIM;
    GemmArgs ga;
    ga.wh0 = whb;           ga.b0 = bq; ga.o0 = qp;
    ga.wh1 = whb + WSZ;     ga.b1 = bk; ga.o1 = kp;
    ga.wh2 = whb + 2 * WSZ; ga.b2 = bv;
    ga.ovh = vh;
    gemm_hmma<<<dim3(DIM / 128, L_TOK / 128, 3), 256, GSMEM>>>(ah, al, ga);

    rmsnorm_rope_split2<<<dim3(L_TOK, 2), 256>>>(qp, kp, gq, gk, qh, ql, kh);

    attention_hmma<<<148, 256, ATT_SMEM>>>(qh, ql, kh, vh, ah, al);

    GemmArgs go;
    go.wh0 = whb + 3 * WSZ; go.b0 = bo; go.o0 = out;
    go.wh1 = go.wh0; go.b1 = bo; go.o1 = out;
    go.wh2 = go.wh0; go.b2 = bo;
    go.ovh = vh;
    gemm_hmma<<<dim3(DIM / 128, L_TOK / 128, 1), 256, GSMEM>>>(ah, al, go);
}

// round 15
// speedup vs baseline: 1.1115x; 1.0541x over previous
#include <cuda_runtime.h>
#include <cuda_fp16.h>
#include <math.h>
#include <stdint.h>

#define L_TOK 3840
#define DIM   1536
#define NH    12
#define HD    128
#define FRAME 480
#define NPAIR 64
#define N_QB  60                      // 64-row q-blocks
#define N_ITEM (N_QB * NH)            // 720

// ---------------- device scratch (no allocs allowed) ----------------
__device__ float g_q[L_TOK * DIM];
__device__ float g_k[L_TOK * DIM];
__device__ float g_cos[L_TOK * NPAIR];
__device__ float g_sin[L_TOK * NPAIR];
__device__ int   g_work[4];
__device__ __half g_ah[L_TOK * DIM];      // A hi (x, later attn out)
__device__ __half g_al[L_TOK * DIM];      // A lo
__device__ __half g_wh[4][DIM * DIM];     // W^T fp16 (single) for q,k,v,o
__device__ __half g_qh[L_TOK * DIM];
__device__ __half g_ql[L_TOK * DIM];
__device__ __half g_kh[L_TOK * DIM];      // K single fp16
__device__ __half g_vh[L_TOK * DIM];      // V single fp16

// =================== sm_80-era PTX helpers (valid on plain sm_103) ==========
__device__ __forceinline__ uint32_t smem_u32(const void* p) {
    uint32_t a;
    asm("{ .reg .u64 t; cvta.to.shared.u64 t, %1; cvt.u32.u64 %0, t; }" : "=r"(a) : "l"(p));
    return a;
}
#define CP_ASYNC16(dst, src) \
    asm volatile("cp.async.cg.shared.global [%0], [%1], 16;" :: "r"(dst), "l"(src))
#define CP_COMMIT() asm volatile("cp.async.commit_group;" ::: "memory")
#define CP_WAIT1()  asm volatile("cp.async.wait_group 1;" ::: "memory")
#define CP_WAIT0()  asm volatile("cp.async.wait_group 0;" ::: "memory")

__device__ __forceinline__ void ldsm4(uint32_t* r, uint32_t addr) {
    asm volatile("ldmatrix.sync.aligned.m8n8.x4.shared.b16 {%0,%1,%2,%3}, [%4];"
                 : "=r"(r[0]), "=r"(r[1]), "=r"(r[2]), "=r"(r[3]) : "r"(addr));
}
__device__ __forceinline__ void ldsm4t(uint32_t* r, uint32_t addr) {
    asm volatile("ldmatrix.sync.aligned.m8n8.x4.trans.shared.b16 {%0,%1,%2,%3}, [%4];"
                 : "=r"(r[0]), "=r"(r[1]), "=r"(r[2]), "=r"(r[3]) : "r"(addr));
}
__device__ __forceinline__ void mma16816(float* c, const uint32_t* a, const uint32_t* b) {
    asm volatile("mma.sync.aligned.m16n8k16.row.col.f32.f16.f16.f32 "
                 "{%0,%1,%2,%3}, {%4,%5,%6,%7}, {%8,%9}, {%0,%1,%2,%3};"
                 : "+f"(c[0]), "+f"(c[1]), "+f"(c[2]), "+f"(c[3])
                 : "r"(a[0]), "r"(a[1]), "r"(a[2]), "r"(a[3]), "r"(b[0]), "r"(b[1]));
}
#define SWZ128(off) ((off) ^ (((off) >> 3) & 0x70))

__device__ __forceinline__ uint32_t pack_f16(float lo, float hi) {
    uint32_t r;
    asm("cvt.rn.f16x2.f32 %0, %1, %2;" : "=r"(r) : "f"(hi), "f"(lo));
    return r;
}

// ---------------- angle table ----------------
__global__ void angles_kernel(const float* __restrict__ ff,
                              const float* __restrict__ fh,
                              const float* __restrict__ fw) {
    int idx = blockIdx.x * blockDim.x + threadIdx.x;
    if (idx >= L_TOK * NPAIR) return;
    int l = idx / NPAIR, j = idx % NPAIR;
    int f = l / FRAME, r = l % FRAME;
    int h = r / 30, w = r % 30;
    float a;
    if (j < 22)      a = ff[f * 22 + j];
    else if (j < 43) a = fh[h * 21 + (j - 22)];
    else             a = fw[w * 21 + (j - 43)];
    g_cos[idx] = cosf(a);
    g_sin[idx] = sinf(a);
}

// ---------------- split fp32 -> fp16 hi/lo ----------------
__global__ __launch_bounds__(256) void split_kernel(const float* __restrict__ x,
                                                    __half* __restrict__ hi,
                                                    __half* __restrict__ lo, int n) {
    int i = blockIdx.x * blockDim.x + threadIdx.x;
    if (i * 4 >= n) return;
    float4 v = *(const float4*)&x[i * 4];
    __half h0 = __float2half(v.x), h1 = __float2half(v.y);
    __half h2 = __float2half(v.z), h3 = __float2half(v.w);
    __half l0 = __float2half(v.x - __half2float(h0));
    __half l1 = __float2half(v.y - __half2float(h1));
    __half l2 = __float2half(v.z - __half2float(h2));
    __half l3 = __float2half(v.w - __half2float(h3));
    __half2* ph = (__half2*)&hi[i * 4];
    __half2* pl = (__half2*)&lo[i * 4];
    ph[0] = {h0, h1}; ph[1] = {h2, h3};
    pl[0] = {l0, l1}; pl[1] = {l2, l3};
}

// ------- fused transpose of 4 weights [K,N] -> [N,K], single fp16 -------
__global__ __launch_bounds__(256) void transpose_half4_kernel(
    const float* __restrict__ W0, const float* __restrict__ W1,
    const float* __restrict__ W2, const float* __restrict__ W3,
    __half* __restrict__ ThBase) {
    __shared__ float t[32][33];
    int z = blockIdx.z;
    const float* W = (z == 0) ? W0 : (z == 1) ? W1 : (z == 2) ? W2 : W3;
    __half* Th = ThBase + (size_t)z * DIM * DIM;
    int tx = threadIdx.x, ty = threadIdx.y;  // 32 x 8
    int x0 = blockIdx.x * 32, y0 = blockIdx.y * 32;
#pragma unroll
    for (int i = 0; i < 32; i += 8)
        t[ty + i][tx] = W[(size_t)(y0 + ty + i) * DIM + x0 + tx];
    __syncthreads();
#pragma unroll
    for (int i = 0; i < 32; i += 8)
        Th[(size_t)(x0 + ty + i) * DIM + y0 + tx] = __float2half(t[tx][ty + i]);
}

// ------- HMMA fp16 2-term GEMM: BK=64, 256t, 2 CTAs/SM (R14 layout) -----
#define GK       64
#define TILE_B   16384
#define BUF_B    (3 * TILE_B)
#define GSMEM    (1024 + 2 * BUF_B)

struct GemmArgs {
    const __half *wh0, *wh1, *wh2;
    const float *b0, *b1, *b2;
    float *o0, *o1;
    __half *ovh;
};

__global__ __launch_bounds__(256, 2) void gemm_hmma(const __half* __restrict__ Ah,
                                                    const __half* __restrict__ Al,
                                                    GemmArgs ga) {
    extern __shared__ char dsm[];
    uint32_t raw = smem_u32(dsm);
    uint32_t sbase = (raw + 1023u) & ~1023u;

    int tid = threadIdx.x;
    int wid = tid >> 5, lane = tid & 31;
    int m0 = blockIdx.y * 128;
    int n0 = blockIdx.x * 128;

    const __half* Bh;
    const float* bias;
    float* Cf;
    if (blockIdx.z == 0)      { Bh = ga.wh0; bias = ga.b0; Cf = ga.o0; }
    else if (blockIdx.z == 1) { Bh = ga.wh1; bias = ga.b1; Cf = ga.o1; }
    else                      { Bh = ga.wh2; bias = ga.b2; Cf = nullptr; }

    const __half* srcs[3] = {Ah, Al, Bh};
    const int rbase[3] = {m0, m0, n0};

    auto load_chunk = [&](int c, int buf) {
        uint32_t dst0 = sbase + (uint32_t)buf * BUF_B;
#pragma unroll
        for (int it = 0; it < 12; it++) {
            int idx = it * 256 + tid;
            int tile = idx >> 10;
            int rem = idx & 1023;
            int r = rem >> 3, g = rem & 7;
            const __half* src = srcs[tile] + (size_t)(rbase[tile] + r) * DIM + c * GK + g * 8;
            uint32_t off = (uint32_t)(r * 128 + g * 16);
            CP_ASYNC16(dst0 + (uint32_t)tile * TILE_B + SWZ128(off), src);
        }
    };

    float Creg[2][8][4];
#pragma unroll
    for (int mt = 0; mt < 2; mt++)
#pragma unroll
        for (int nf = 0; nf < 8; nf++)
#pragma unroll
            for (int j = 0; j < 4; j++) Creg[mt][nf][j] = 0.f;

    int m_base = (wid & 3) * 32;
    int n_base = (wid >> 2) * 64;
    int a_r = m_base + (lane & 7) + ((lane >> 3) & 1) * 8;
    int a_g = (lane >> 4);
    int b_r = n_base + ((lane >> 4) & 1) * 8 + (lane & 7);
    int b_g = (lane >> 3) & 1;

    const int NCH = DIM / GK;
    load_chunk(0, 0); CP_COMMIT();
    load_chunk(1, 1); CP_COMMIT();

    for (int c = 0; c < NCH; c++) {
        if (c == NCH - 1) CP_WAIT0(); else CP_WAIT1();
        __syncthreads();

        int buf = c & 1;
        uint32_t sb = sbase + (uint32_t)buf * BUF_B;
        uint32_t sAh = sb, sAl = sb + TILE_B, sBh = sb + 2 * TILE_B;

#pragma unroll
        for (int ks = 0; ks < 4; ks++) {
            uint32_t ah[2][4], al[2][4];
#pragma unroll
            for (int mt = 0; mt < 2; mt++) {
                uint32_t off = SWZ128((uint32_t)((a_r + mt * 16) * 128 + ((a_g + 2 * ks) * 16)));
                ldsm4(ah[mt], sAh + off);
                ldsm4(al[mt], sAl + off);
            }
#pragma unroll
            for (int grp = 0; grp < 2; grp++) {
                uint32_t bh[8];
#pragma unroll
                for (int half = 0; half < 2; half++) {
                    int nf2 = grp * 2 + half;
                    uint32_t off = SWZ128((uint32_t)((b_r + nf2 * 16) * 128 + ((b_g + 2 * ks) * 16)));
                    ldsm4(&bh[half * 4], sBh + off);
                }
#pragma unroll
                for (int nfl = 0; nfl < 4; nfl++)
#pragma unroll
                    for (int mt = 0; mt < 2; mt++)
                        mma16816(Creg[mt][grp * 4 + nfl], ah[mt], &bh[nfl * 2]);
#pragma unroll
                for (int nfl = 0; nfl < 4; nfl++)
#pragma unroll
                    for (int mt = 0; mt < 2; mt++)
                        mma16816(Creg[mt][grp * 4 + nfl], al[mt], &bh[nfl * 2]);
            }
        }
        __syncthreads();
        if (c + 2 < NCH) { load_chunk(c + 2, buf); CP_COMMIT(); }
    }

#pragma unroll
    for (int mt = 0; mt < 2; mt++) {
#pragma unroll
        for (int nf = 0; nf < 8; nf++) {
            int r0 = m0 + m_base + mt * 16 + (lane >> 2);
            int col = n0 + n_base + nf * 8 + (lane & 3) * 2;
            float2 bv = *(const float2*)&bias[col];
            float* cc = Creg[mt][nf];
            float c00 = cc[0] + bv.x, c01 = cc[1] + bv.y;
            float c10 = cc[2] + bv.x, c11 = cc[3] + bv.y;
            if (Cf == nullptr) {
                *(uint32_t*)&ga.ovh[(size_t)r0 * DIM + col] = pack_f16(c00, c01);
                *(uint32_t*)&ga.ovh[(size_t)(r0 + 8) * DIM + col] = pack_f16(c10, c11);
            } else {
                *(float2*)&Cf[(size_t)r0 * DIM + col] = {c00, c01};
                *(float2*)&Cf[(size_t)(r0 + 8) * DIM + col] = {c10, c11};
            }
        }
    }
}

// ---------------- fused RMSNorm + RoPE: q -> fp16 hi/lo, k -> fp16 single ---
__global__ __launch_bounds__(256) void rmsnorm_rope_split2(
    const float* __restrict__ xq, const float* __restrict__ xk,
    const float* __restrict__ gqv, const float* __restrict__ gkv,
    __half* __restrict__ qh, __half* __restrict__ ql,
    __half* __restrict__ kh) {
    int row = blockIdx.x;
    int which = blockIdx.y;
    const float* xp = (which ? xk : xq) + (size_t)row * DIM;
    const float* g = which ? gkv : gqv;
    float outscale = which ? 1.0f : 0.08838834764831845f;
    int tid = threadIdx.x;

    float ss = 0.f;
    for (int i = tid; i < DIM; i += 256) {
        float v = xp[i];
        ss += v * v;
    }
    __shared__ float red[8];
#pragma unroll
    for (int m = 16; m; m >>= 1) ss += __shfl_xor_sync(0xffffffffu, ss, m);
    if ((tid & 31) == 0) red[tid >> 5] = ss;
    __syncthreads();
    if (tid < 8) {
        float v = red[tid];
#pragma unroll
        for (int m = 4; m; m >>= 1) v += __shfl_xor_sync(0xffu, v, m);
        if (tid == 0) red[0] = rsqrtf(v * (1.0f / DIM) + 1e-6f);
    }
    __syncthreads();
    float scale = red[0];

    for (int p = tid; p < NH * NPAIR; p += 256) {
        int head = p >> 6, j = p & 63;
        int i0 = head * HD + 2 * j;
        float2 v = *(const float2*)&xp[i0];
        float2 gv = *(const float2*)&g[i0];
        float xr = v.x * scale * gv.x;
        float xi = v.y * scale * gv.y;
        float c = g_cos[row * NPAIR + j];
        float s = g_sin[row * NPAIR + j];
        float yr = (xr * c - xi * s) * outscale;
        float yi = (xr * s + xi * c) * outscale;
        if (which == 0) {
            __half hr = __float2half(yr);
            __half hi2 = __float2half(yi);
            __half lr = __float2half(yr - __half2float(hr));
            __half li = __float2half(yi - __half2float(hi2));
            *(__half2*)&qh[(size_t)row * DIM + i0] = {hr, hi2};
            *(__half2*)&ql[(size_t)row * DIM + i0] = {lr, li};
        } else {
            *(__half2*)&kh[(size_t)row * DIM + i0] = {__float2half(yr), __float2half(yi)};
        }
    }
}

// ------- persistent fp16 flash attention: q-tile 64, 128t, 2 CTAs/SM --------
// Smem/CTA: Qh 16K + Ql 16K @0; K-ring 2x16K @32768; V-ring 3x16K @65536;
// work slot @114688. Total 114720 B -> 2 CTAs/SM.
#define ATT_Q    0
#define ATT_K    32768
#define ATT_V    65536
#define ATT_WS   114688
#define ATT_SMEM (114688 + 32)

__global__ __launch_bounds__(128, 2) void attention_hmma(
    const __half* __restrict__ Qh, const __half* __restrict__ Ql,
    const __half* __restrict__ Kh, const __half* __restrict__ Vh,
    __half* __restrict__ Oh, __half* __restrict__ Ol) {
    extern __shared__ char dsm[];
    uint32_t sbase = smem_u32(dsm);
    int* wslot = (int*)(dsm + ATT_WS);

    int tid = threadIdx.x, wid = tid >> 5, lane = tid & 31;

    int a_r = wid * 16 + (lane & 7) + ((lane >> 3) & 1) * 8;
    int a_half = lane >> 4;
    int b_r = ((lane >> 4) & 1) * 8 + (lane & 7);
    int b_half = (lane >> 3) & 1;
    int v_r = (lane & 15);
    int vg = (lane >> 4);

    for (;;) {
        if (tid == 0) wslot[0] = atomicAdd(&g_work[1], 1);
        __syncthreads();
        int item = wslot[0];
        if (item >= N_ITEM) return;
        int qb = N_QB - 1 - item / NH;   // heavy-first
        int h = item % NH;
        int q0 = qb * 64;

        // ---- load Q (hi+lo), 64 rows x 256B, subtile layout ----
        {
            const __half* gq[2] = {Qh, Ql};
#pragma unroll
            for (int op = 0; op < 2; op++) {
                const __half* src = gq[op] + (size_t)q0 * DIM + h * HD;
                uint32_t dst = sbase + ATT_Q + (uint32_t)op * 16384;
#pragma unroll
                for (int it = 0; it < 8; it++) {
                    int idx = it * 128 + tid;
                    int r = idx >> 4, gg = idx & 15;
                    uint32_t off = (uint32_t)((gg >> 3) * 8192) + SWZ128((uint32_t)(r * 128 + (gg & 7) * 16));
                    CP_ASYNC16(dst + off, src + (size_t)r * DIM + gg * 8);
                }
            }
            CP_COMMIT();
        }

        auto load_kv = [&](int t) {
            int k0 = t * 64;
            uint32_t kdst = sbase + ATT_K + (uint32_t)(t & 1) * 16384;
            uint32_t vdst = sbase + ATT_V + (uint32_t)(t % 3) * 16384;
            const __half* ksrc = Kh + (size_t)k0 * DIM + h * HD;
            const __half* vsrc = Vh + (size_t)k0 * DIM + h * HD;
#pragma unroll
            for (int it = 0; it < 8; it++) {
                int idx = it * 128 + tid;
                int r = idx >> 4, gg = idx & 15;
                uint32_t off = (uint32_t)((gg >> 3) * 8192) + SWZ128((uint32_t)(r * 128 + (gg & 7) * 16));
                CP_ASYNC16(kdst + off, ksrc + (size_t)r * DIM + gg * 8);
                CP_ASYNC16(vdst + off, vsrc + (size_t)r * DIM + gg * 8);
            }
        };

        float O[16][4];
#pragma unroll
        for (int i = 0; i < 16; i++)
#pragma unroll
            for (int j = 0; j < 4; j++) O[i][j] = 0.f;
        float m0 = -1e30f, m1 = -1e30f, l0 = 0.f, l1 = 0.f;
        uint32_t PhP[4][4], PlP[4][4];

        int r0g = q0 + wid * 16 + (lane >> 2);
        int fr0 = r0g / FRAME, fr1 = (r0g + 8) / FRAME;
        int blkmin_f = q0 / FRAME;
        int fqmax = (q0 + 63) / FRAME;
        int ntile = ((fqmax + 1) * FRAME + 63) >> 6;

        load_kv(0); CP_COMMIT();
        load_kv(1); CP_COMMIT();

        for (int t = 0; t < ntile; t++) {
            if (t == ntile - 1) CP_WAIT0(); else CP_WAIT1();
            __syncthreads();

            int k0 = t * 64;
            uint32_t bKh = sbase + ATT_K + (uint32_t)(t & 1) * 16384;

            // ---- S = Q K^T (2-term) ----
            float S[8][4];
#pragma unroll
            for (int i = 0; i < 8; i++)
#pragma unroll
                for (int j = 0; j < 4; j++) S[i][j] = 0.f;

#pragma unroll
            for (int ks = 0; ks < 8; ks++) {
                uint32_t qa[4], ql4[4], kh4[16];
                uint32_t gq16 = (uint32_t)(((ks & 3) * 2 + a_half) * 16);
                uint32_t aoff = (uint32_t)((ks >> 2) * 8192) + SWZ128((uint32_t)(a_r * 128) + gq16);
                ldsm4(qa, sbase + ATT_Q + aoff);
                ldsm4(ql4, sbase + ATT_Q + 16384 + aoff);
                uint32_t gk16 = (uint32_t)(((ks & 3) * 2 + b_half) * 16);
#pragma unroll
                for (int nb = 0; nb < 4; nb++) {
                    uint32_t boff = (uint32_t)((ks >> 2) * 8192) +
                                    SWZ128((uint32_t)((nb * 16 + b_r) * 128) + gk16);
                    ldsm4(&kh4[nb * 4], bKh + boff);
                }
#pragma unroll
                for (int nf = 0; nf < 8; nf++) mma16816(S[nf], qa, &kh4[nf * 2]);
#pragma unroll
                for (int nf = 0; nf < 8; nf++) mma16816(S[nf], ql4, &kh4[nf * 2]);
            }

            // ---- delayed PV ----
            if (t > 0) {
                uint32_t bVh = sbase + ATT_V + (uint32_t)((t - 1) % 3) * 16384;
#pragma unroll
                for (int j = 0; j < 4; j++) {
#pragma unroll
                    for (int dp = 0; dp < 4; dp++) {
                        int db0 = 2 * dp, db1 = 2 * dp + 1;
                        uint32_t row = (uint32_t)((j * 16 + v_r) * 128);
                        uint32_t voff0 = (uint32_t)((db0 >> 2) * 8192) +
                                         SWZ128(row + (uint32_t)(((db0 & 3) * 2 + vg) * 16));
                        uint32_t voff1 = (uint32_t)((db1 >> 2) * 8192) +
                                         SWZ128(row + (uint32_t)(((db1 & 3) * 2 + vg) * 16));
                        uint32_t vh_a[4], vh_b[4];
                        ldsm4t(vh_a, bVh + voff0);
                        ldsm4t(vh_b, bVh + voff1);
                        float* o0 = O[4 * dp + 0];
                        float* o1 = O[4 * dp + 1];
                        float* o2 = O[4 * dp + 2];
                        float* o3 = O[4 * dp + 3];
                        mma16816(o0, PhP[j], &vh_a[0]);
                        mma16816(o1, PhP[j], &vh_a[2]);
                        mma16816(o2, PhP[j], &vh_b[0]);
                        mma16816(o3, PhP[j], &vh_b[2]);
                        mma16816(o0, PlP[j], &vh_a[0]);
                        mma16816(o1, PlP[j], &vh_a[2]);
                        mma16816(o2, PlP[j], &vh_b[0]);
                        mma16816(o3, PlP[j], &vh_b[2]);
                    }
                }
            }

            // ---- mask ----
            if ((k0 + 63) / FRAME > blkmin_f) {
#pragma unroll
                for (int nf = 0; nf < 8; nf++) {
                    int c = k0 + nf * 8 + 2 * (lane & 3);
                    int cf0 = c / FRAME, cf1 = (c + 1) / FRAME;
                    if (cf0 > fr0) S[nf][0] = -1e30f;
                    if (cf1 > fr0) S[nf][1] = -1e30f;
                    if (cf0 > fr1) S[nf][2] = -1e30f;
                    if (cf1 > fr1) S[nf][3] = -1e30f;
                }
            }

            // ---- online softmax ----
            float mx0 = -1e30f, mx1 = -1e30f;
#pragma unroll
            for (int nf = 0; nf < 8; nf++) {
                mx0 = fmaxf(mx0, fmaxf(S[nf][0], S[nf][1]));
                mx1 = fmaxf(mx1, fmaxf(S[nf][2], S[nf][3]));
            }
            mx0 = fmaxf(mx0, __shfl_xor_sync(0xffffffffu, mx0, 1));
            mx0 = fmaxf(mx0, __shfl_xor_sync(0xffffffffu, mx0, 2));
            mx1 = fmaxf(mx1, __shfl_xor_sync(0xffffffffu, mx1, 1));
            mx1 = fmaxf(mx1, __shfl_xor_sync(0xffffffffu, mx1, 2));
            float mn0 = fmaxf(m0, mx0), mn1 = fmaxf(m1, mx1);
            float al0 = __expf(m0 - mn0), al1 = __expf(m1 - mn1);
            m0 = mn0; m1 = mn1;
#pragma unroll
            for (int i = 0; i < 16; i++) {
                O[i][0] *= al0; O[i][1] *= al0;
                O[i][2] *= al1; O[i][3] *= al1;
            }

            float ps0 = 0.f, ps1 = 0.f;
#pragma unroll
            for (int j = 0; j < 4; j++) {
                float p00 = __expf(S[2 * j][0] - mn0);
                float p01 = __expf(S[2 * j][1] - mn0);
                float p02 = __expf(S[2 * j][2] - mn1);
                float p03 = __expf(S[2 * j][3] - mn1);
                float p10 = __expf(S[2 * j + 1][0] - mn0);
                float p11 = __expf(S[2 * j + 1][1] - mn0);
                float p12 = __expf(S[2 * j + 1][2] - mn1);
                float p13 = __expf(S[2 * j + 1][3] - mn1);
                ps0 += (p00 + p01) + (p10 + p11);
                ps1 += (p02 + p03) + (p12 + p13);
                PhP[j][0] = pack_f16(p00, p01);
                PhP[j][1] = pack_f16(p02, p03);
                PhP[j][2] = pack_f16(p10, p11);
                PhP[j][3] = pack_f16(p12, p13);
                __half2 h0 = *(__half2*)&PhP[j][0];
                __half2 h1 = *(__half2*)&PhP[j][1];
                __half2 h2 = *(__half2*)&PhP[j][2];
                __half2 h3 = *(__half2*)&PhP[j][3];
                PlP[j][0] = pack_f16(p00 - __half2float(h0.x), p01 - __half2float(h0.y));
                PlP[j][1] = pack_f16(p02 - __half2float(h1.x), p03 - __half2float(h1.y));
                PlP[j][2] = pack_f16(p10 - __half2float(h2.x), p11 - __half2float(h2.y));
                PlP[j][3] = pack_f16(p12 - __half2float(h3.x), p13 - __half2float(h3.y));
            }
            ps0 += __shfl_xor_sync(0xffffffffu, ps0, 1);
            ps0 += __shfl_xor_sync(0xffffffffu, ps0, 2);
            ps1 += __shfl_xor_sync(0xffffffffu, ps1, 1);
            ps1 += __shfl_xor_sync(0xffffffffu, ps1, 2);
            l0 = l0 * al0 + ps0;
            l1 = l1 * al1 + ps1;

            __syncthreads();
            if (t + 2 < ntile) { load_kv(t + 2); CP_COMMIT(); }
        }

        // ---- final PV ----
        {
            uint32_t bVh = sbase + ATT_V + (uint32_t)((ntile - 1) % 3) * 16384;
#pragma unroll
            for (int j = 0; j < 4; j++) {
#pragma unroll
                for (int dp = 0; dp < 4; dp++) {
                    int db0 = 2 * dp, db1 = 2 * dp + 1;
                    uint32_t row = (uint32_t)((j * 16 + v_r) * 128);
                    uint32_t voff0 = (uint32_t)((db0 >> 2) * 8192) +
                                     SWZ128(row + (uint32_t)(((db0 & 3) * 2 + vg) * 16));
                    uint32_t voff1 = (uint32_t)((db1 >> 2) * 8192) +
                                     SWZ128(row + (uint32_t)(((db1 & 3) * 2 + vg) * 16));
                    uint32_t vh_a[4], vh_b[4];
                    ldsm4t(vh_a, bVh + voff0);
                    ldsm4t(vh_b, bVh + voff1);
                    float* o0 = O[4 * dp + 0];
                    float* o1 = O[4 * dp + 1];
                    float* o2 = O[4 * dp + 2];
                    float* o3 = O[4 * dp + 3];
                    mma16816(o0, PhP[j], &vh_a[0]);
                    mma16816(o1, PhP[j], &vh_a[2]);
                    mma16816(o2, PhP[j], &vh_b[0]);
                    mma16816(o3, PhP[j], &vh_b[2]);
                    mma16816(o0, PlP[j], &vh_a[0]);
                    mma16816(o1, PlP[j], &vh_a[2]);
                    mma16816(o2, PlP[j], &vh_b[0]);
                    mma16816(o3, PlP[j], &vh_b[2]);
                }
            }
        }

        // ---- epilogue: normalize, split to fp16 hi/lo, store ----
        float inv0 = 1.0f / l0, inv1 = 1.0f / l1;
        int row0 = q0 + wid * 16 + (lane >> 2);
#pragma unroll
        for (int nf = 0; nf < 16; nf++) {
            int col = h * HD + nf * 8 + 2 * (lane & 3);
            float o00 = O[nf][0] * inv0, o01 = O[nf][1] * inv0;
            float o10 = O[nf][2] * inv1, o11 = O[nf][3] * inv1;
            uint32_t h0 = pack_f16(o00, o01);
            uint32_t h1 = pack_f16(o10, o11);
            __half2 hh0 = *(__half2*)&h0;
            __half2 hh1 = *(__half2*)&h1;
            uint32_t lo0 = pack_f16(o00 - __half2float(hh0.x), o01 - __half2float(hh0.y));
            uint32_t lo1 = pack_f16(o10 - __half2float(hh1.x), o11 - __half2float(hh1.y));
            *(uint32_t*)&Oh[(size_t)row0 * DIM + col] = h0;
            *(uint32_t*)&Ol[(size_t)row0 * DIM + col] = lo0;
            *(uint32_t*)&Oh[(size_t)(row0 + 8) * DIM + col] = h1;
            *(uint32_t*)&Ol[(size_t)(row0 + 8) * DIM + col] = lo1;
        }
    }
}

// ---------------- launch ----------------
extern "C" void kernel_launch(void* const* d_in, const int* in_sizes, int n_in,
                              void* d_out, int out_size) {
    const float* x  = (const float*)d_in[0];
    const float* Wq = (const float*)d_in[1];
    const float* bq = (const float*)d_in[2];
    const float* Wk = (const float*)d_in[3];
    const float* bk = (const float*)d_in[4];
    const float* Wv = (const float*)d_in[5];
    const float* bv = (const float*)d_in[6];
    const float* Wo = (const float*)d_in[7];
    const float* bo = (const float*)d_in[8];
    const float* gq = (const float*)d_in[9];
    const float* gk = (const float*)d_in[10];
    const float* ff = (const float*)d_in[11];
    const float* fh = (const float*)d_in[12];
    const float* fw = (const float*)d_in[13];
    float* out = (float*)d_out;

    float *qp, *kp;
    __half *ah, *al, *qh, *ql, *kh, *vh, *whb;
    int* workp;
    cudaGetSymbolAddress((void**)&qp, g_q);
    cudaGetSymbolAddress((void**)&kp, g_k);
    cudaGetSymbolAddress((void**)&ah, g_ah);
    cudaGetSymbolAddress((void**)&al, g_al);
    cudaGetSymbolAddress((void**)&whb, g_wh);
    cudaGetSymbolAddress((void**)&qh, g_qh);
    cudaGetSymbolAddress((void**)&ql, g_ql);
    cudaGetSymbolAddress((void**)&kh, g_kh);
    cudaGetSymbolAddress((void**)&vh, g_vh);
    cudaGetSymbolAddress((void**)&workp, g_work);

    cudaFuncSetAttribute(gemm_hmma,
                         cudaFuncAttributeMaxDynamicSharedMemorySize, GSMEM);
    cudaFuncSetAttribute(attention_hmma,
                         cudaFuncAttributeMaxDynamicSharedMemorySize, ATT_SMEM);

    cudaMemsetAsync(workp, 0, 4 * sizeof(int));

    angles_kernel<<<(L_TOK * NPAIR + 255) / 256, 256>>>(ff, fh, fw);

    const int NELT = L_TOK * DIM;
    split_kernel<<<(NELT / 4 + 255) / 256, 256>>>(x, ah, al, NELT);

    transpose_half4_kernel<<<dim3(DIM / 32, DIM / 32, 4), dim3(32, 8)>>>(
        Wq, Wk, Wv, Wo, whb);

    const size_t WSZ = (size_t)DIM * DIM;
    GemmArgs ga;
    ga.wh0 = whb;           ga.b0 = bq; ga.o0 = qp;
    ga.wh1 = whb + WSZ;     ga.b1 = bk; ga.o1 = kp;
    ga.wh2 = whb + 2 * WSZ; ga.b2 = bv;
    ga.ovh = vh;
    gemm_hmma<<<dim3(DIM / 128, L_TOK / 128, 3), 256, GSMEM>>>(ah, al, ga);

    rmsnorm_rope_split2<<<dim3(L_TOK, 2), 256>>>(qp, kp, gq, gk, qh, ql, kh);

    attention_hmma<<<296, 128, ATT_SMEM>>>(qh, ql, kh, vh, ah, al);

    GemmArgs go;
    go.wh0 = whb + 3 * WSZ; go.b0 = bo; go.o0 = out;
    go.wh1 = go.wh0; go.b1 = bo; go.o1 = out;
    go.wh2 = go.wh0; go.b2 = bo;
    go.ovh = vh;
    gemm_hmma<<<dim3(DIM / 128, L_TOK / 128, 1), 256, GSMEM>>>(ah, al, go);
}

// round 16
// speedup vs baseline: 1.2766x; 1.1485x over previous
#include <cuda_runtime.h>
#include <cuda_fp16.h>
#include <math.h>
#include <stdint.h>

#define L_TOK 3840
#define DIM   1536
#define NH    12
#define HD    128
#define FRAME 480
#define NPAIR 64
#define N_QB  60                      // 64-row q-blocks
#define N_ITEM (N_QB * NH)            // 720

// ---------------- device scratch (no allocs allowed) ----------------
__device__ float g_q[L_TOK * DIM];
__device__ float g_k[L_TOK * DIM];
__device__ float g_cos[L_TOK * NPAIR];
__device__ float g_sin[L_TOK * NPAIR];
__device__ int   g_work[4];
__device__ __half g_ah[L_TOK * DIM];      // A hi (x, later attn out)
__device__ __half g_al[L_TOK * DIM];      // A lo
__device__ __half g_wh[4][DIM * DIM];     // W^T fp16 (single) for q,k,v,o
__device__ __half g_qh[L_TOK * DIM];      // Q single fp16
__device__ __half g_kh[L_TOK * DIM];      // K single fp16
__device__ __half g_vh[L_TOK * DIM];      // V single fp16

// =================== sm_80-era PTX helpers (valid on plain sm_103) ==========
__device__ __forceinline__ uint32_t smem_u32(const void* p) {
    uint32_t a;
    asm("{ .reg .u64 t; cvta.to.shared.u64 t, %1; cvt.u32.u64 %0, t; }" : "=r"(a) : "l"(p));
    return a;
}
#define CP_ASYNC16(dst, src) \
    asm volatile("cp.async.cg.shared.global [%0], [%1], 16;" :: "r"(dst), "l"(src))
#define CP_COMMIT() asm volatile("cp.async.commit_group;" ::: "memory")
#define CP_WAIT1()  asm volatile("cp.async.wait_group 1;" ::: "memory")
#define CP_WAIT0()  asm volatile("cp.async.wait_group 0;" ::: "memory")

__device__ __forceinline__ void ldsm4(uint32_t* r, uint32_t addr) {
    asm volatile("ldmatrix.sync.aligned.m8n8.x4.shared.b16 {%0,%1,%2,%3}, [%4];"
                 : "=r"(r[0]), "=r"(r[1]), "=r"(r[2]), "=r"(r[3]) : "r"(addr));
}
__device__ __forceinline__ void ldsm4t(uint32_t* r, uint32_t addr) {
    asm volatile("ldmatrix.sync.aligned.m8n8.x4.trans.shared.b16 {%0,%1,%2,%3}, [%4];"
                 : "=r"(r[0]), "=r"(r[1]), "=r"(r[2]), "=r"(r[3]) : "r"(addr));
}
__device__ __forceinline__ void mma16816(float* c, const uint32_t* a, const uint32_t* b) {
    asm volatile("mma.sync.aligned.m16n8k16.row.col.f32.f16.f16.f32 "
                 "{%0,%1,%2,%3}, {%4,%5,%6,%7}, {%8,%9}, {%0,%1,%2,%3};"
                 : "+f"(c[0]), "+f"(c[1]), "+f"(c[2]), "+f"(c[3])
                 : "r"(a[0]), "r"(a[1]), "r"(a[2]), "r"(a[3]), "r"(b[0]), "r"(b[1]));
}
#define SWZ128(off) ((off) ^ (((off) >> 3) & 0x70))

__device__ __forceinline__ uint32_t pack_f16(float lo, float hi) {
    uint32_t r;
    asm("cvt.rn.f16x2.f32 %0, %1, %2;" : "=r"(r) : "f"(hi), "f"(lo));
    return r;
}

// ---------------- angle table ----------------
__global__ void angles_kernel(const float* __restrict__ ff,
                              const float* __restrict__ fh,
                              const float* __restrict__ fw) {
    int idx = blockIdx.x * blockDim.x + threadIdx.x;
    if (idx >= L_TOK * NPAIR) return;
    int l = idx / NPAIR, j = idx % NPAIR;
    int f = l / FRAME, r = l % FRAME;
    int h = r / 30, w = r % 30;
    float a;
    if (j < 22)      a = ff[f * 22 + j];
    else if (j < 43) a = fh[h * 21 + (j - 22)];
    else             a = fw[w * 21 + (j - 43)];
    g_cos[idx] = cosf(a);
    g_sin[idx] = sinf(a);
}

// ---------------- split fp32 -> fp16 hi/lo ----------------
__global__ __launch_bounds__(256) void split_kernel(const float* __restrict__ x,
                                                    __half* __restrict__ hi,
                                                    __half* __restrict__ lo, int n) {
    int i = blockIdx.x * blockDim.x + threadIdx.x;
    if (i * 4 >= n) return;
    float4 v = *(const float4*)&x[i * 4];
    __half h0 = __float2half(v.x), h1 = __float2half(v.y);
    __half h2 = __float2half(v.z), h3 = __float2half(v.w);
    __half l0 = __float2half(v.x - __half2float(h0));
    __half l1 = __float2half(v.y - __half2float(h1));
    __half l2 = __float2half(v.z - __half2float(h2));
    __half l3 = __float2half(v.w - __half2float(h3));
    __half2* ph = (__half2*)&hi[i * 4];
    __half2* pl = (__half2*)&lo[i * 4];
    ph[0] = {h0, h1}; ph[1] = {h2, h3};
    pl[0] = {l0, l1}; pl[1] = {l2, l3};
}

// ------- fused transpose of 4 weights [K,N] -> [N,K], single fp16 -------
__global__ __launch_bounds__(256) void transpose_half4_kernel(
    const float* __restrict__ W0, const float* __restrict__ W1,
    const float* __restrict__ W2, const float* __restrict__ W3,
    __half* __restrict__ ThBase) {
    __shared__ float t[32][33];
    int z = blockIdx.z;
    const float* W = (z == 0) ? W0 : (z == 1) ? W1 : (z == 2) ? W2 : W3;
    __half* Th = ThBase + (size_t)z * DIM * DIM;
    int tx = threadIdx.x, ty = threadIdx.y;  // 32 x 8
    int x0 = blockIdx.x * 32, y0 = blockIdx.y * 32;
#pragma unroll
    for (int i = 0; i < 32; i += 8)
        t[ty + i][tx] = W[(size_t)(y0 + ty + i) * DIM + x0 + tx];
    __syncthreads();
#pragma unroll
    for (int i = 0; i < 32; i += 8)
        Th[(size_t)(x0 + ty + i) * DIM + y0 + tx] = __float2half(t[tx][ty + i]);
}

// ------- HMMA fp16 2-term GEMM: BK=64, 256t, 2 CTAs/SM (R14 layout) -----
#define GK       64
#define TILE_B   16384
#define BUF_B    (3 * TILE_B)
#define GSMEM    (1024 + 2 * BUF_B)

struct GemmArgs {
    const __half *wh0, *wh1, *wh2;
    const float *b0, *b1, *b2;
    float *o0, *o1;
    __half *ovh;
};

__global__ __launch_bounds__(256, 2) void gemm_hmma(const __half* __restrict__ Ah,
                                                    const __half* __restrict__ Al,
                                                    GemmArgs ga) {
    extern __shared__ char dsm[];
    uint32_t raw = smem_u32(dsm);
    uint32_t sbase = (raw + 1023u) & ~1023u;

    int tid = threadIdx.x;
    int wid = tid >> 5, lane = tid & 31;
    int m0 = blockIdx.y * 128;
    int n0 = blockIdx.x * 128;

    const __half* Bh;
    const float* bias;
    float* Cf;
    if (blockIdx.z == 0)      { Bh = ga.wh0; bias = ga.b0; Cf = ga.o0; }
    else if (blockIdx.z == 1) { Bh = ga.wh1; bias = ga.b1; Cf = ga.o1; }
    else                      { Bh = ga.wh2; bias = ga.b2; Cf = nullptr; }

    const __half* srcs[3] = {Ah, Al, Bh};
    const int rbase[3] = {m0, m0, n0};

    auto load_chunk = [&](int c, int buf) {
        uint32_t dst0 = sbase + (uint32_t)buf * BUF_B;
#pragma unroll
        for (int it = 0; it < 12; it++) {
            int idx = it * 256 + tid;
            int tile = idx >> 10;
            int rem = idx & 1023;
            int r = rem >> 3, g = rem & 7;
            const __half* src = srcs[tile] + (size_t)(rbase[tile] + r) * DIM + c * GK + g * 8;
            uint32_t off = (uint32_t)(r * 128 + g * 16);
            CP_ASYNC16(dst0 + (uint32_t)tile * TILE_B + SWZ128(off), src);
        }
    };

    float Creg[2][8][4];
#pragma unroll
    for (int mt = 0; mt < 2; mt++)
#pragma unroll
        for (int nf = 0; nf < 8; nf++)
#pragma unroll
            for (int j = 0; j < 4; j++) Creg[mt][nf][j] = 0.f;

    int m_base = (wid & 3) * 32;
    int n_base = (wid >> 2) * 64;
    int a_r = m_base + (lane & 7) + ((lane >> 3) & 1) * 8;
    int a_g = (lane >> 4);
    int b_r = n_base + ((lane >> 4) & 1) * 8 + (lane & 7);
    int b_g = (lane >> 3) & 1;

    const int NCH = DIM / GK;
    load_chunk(0, 0); CP_COMMIT();
    load_chunk(1, 1); CP_COMMIT();

    for (int c = 0; c < NCH; c++) {
        if (c == NCH - 1) CP_WAIT0(); else CP_WAIT1();
        __syncthreads();

        int buf = c & 1;
        uint32_t sb = sbase + (uint32_t)buf * BUF_B;
        uint32_t sAh = sb, sAl = sb + TILE_B, sBh = sb + 2 * TILE_B;

#pragma unroll
        for (int ks = 0; ks < 4; ks++) {
            uint32_t ah[2][4], al[2][4];
#pragma unroll
            for (int mt = 0; mt < 2; mt++) {
                uint32_t off = SWZ128((uint32_t)((a_r + mt * 16) * 128 + ((a_g + 2 * ks) * 16)));
                ldsm4(ah[mt], sAh + off);
                ldsm4(al[mt], sAl + off);
            }
#pragma unroll
            for (int grp = 0; grp < 2; grp++) {
                uint32_t bh[8];
#pragma unroll
                for (int half = 0; half < 2; half++) {
                    int nf2 = grp * 2 + half;
                    uint32_t off = SWZ128((uint32_t)((b_r + nf2 * 16) * 128 + ((b_g + 2 * ks) * 16)));
                    ldsm4(&bh[half * 4], sBh + off);
                }
#pragma unroll
                for (int nfl = 0; nfl < 4; nfl++)
#pragma unroll
                    for (int mt = 0; mt < 2; mt++)
                        mma16816(Creg[mt][grp * 4 + nfl], ah[mt], &bh[nfl * 2]);
#pragma unroll
                for (int nfl = 0; nfl < 4; nfl++)
#pragma unroll
                    for (int mt = 0; mt < 2; mt++)
                        mma16816(Creg[mt][grp * 4 + nfl], al[mt], &bh[nfl * 2]);
            }
        }
        __syncthreads();
        if (c + 2 < NCH) { load_chunk(c + 2, buf); CP_COMMIT(); }
    }

#pragma unroll
    for (int mt = 0; mt < 2; mt++) {
#pragma unroll
        for (int nf = 0; nf < 8; nf++) {
            int r0 = m0 + m_base + mt * 16 + (lane >> 2);
            int col = n0 + n_base + nf * 8 + (lane & 3) * 2;
            float2 bv = *(const float2*)&bias[col];
            float* cc = Creg[mt][nf];
            float c00 = cc[0] + bv.x, c01 = cc[1] + bv.y;
            float c10 = cc[2] + bv.x, c11 = cc[3] + bv.y;
            if (Cf == nullptr) {
                *(uint32_t*)&ga.ovh[(size_t)r0 * DIM + col] = pack_f16(c00, c01);
                *(uint32_t*)&ga.ovh[(size_t)(r0 + 8) * DIM + col] = pack_f16(c10, c11);
            } else {
                *(float2*)&Cf[(size_t)r0 * DIM + col] = {c00, c01};
                *(float2*)&Cf[(size_t)(r0 + 8) * DIM + col] = {c10, c11};
            }
        }
    }
}

// ------- fused RMSNorm + RoPE: q -> fp16 single, k -> fp16 single -------
__global__ __launch_bounds__(256) void rmsnorm_rope_split2(
    const float* __restrict__ xq, const float* __restrict__ xk,
    const float* __restrict__ gqv, const float* __restrict__ gkv,
    __half* __restrict__ qh, __half* __restrict__ kh) {
    int row = blockIdx.x;
    int which = blockIdx.y;
    const float* xp = (which ? xk : xq) + (size_t)row * DIM;
    const float* g = which ? gkv : gqv;
    __half* oh = which ? kh : qh;
    float outscale = which ? 1.0f : 0.08838834764831845f;
    int tid = threadIdx.x;

    float ss = 0.f;
    for (int i = tid; i < DIM; i += 256) {
        float v = xp[i];
        ss += v * v;
    }
    __shared__ float red[8];
#pragma unroll
    for (int m = 16; m; m >>= 1) ss += __shfl_xor_sync(0xffffffffu, ss, m);
    if ((tid & 31) == 0) red[tid >> 5] = ss;
    __syncthreads();
    if (tid < 8) {
        float v = red[tid];
#pragma unroll
        for (int m = 4; m; m >>= 1) v += __shfl_xor_sync(0xffu, v, m);
        if (tid == 0) red[0] = rsqrtf(v * (1.0f / DIM) + 1e-6f);
    }
    __syncthreads();
    float scale = red[0];

    for (int p = tid; p < NH * NPAIR; p += 256) {
        int head = p >> 6, j = p & 63;
        int i0 = head * HD + 2 * j;
        float2 v = *(const float2*)&xp[i0];
        float2 gv = *(const float2*)&g[i0];
        float xr = v.x * scale * gv.x;
        float xi = v.y * scale * gv.y;
        float c = g_cos[row * NPAIR + j];
        float s = g_sin[row * NPAIR + j];
        float yr = (xr * c - xi * s) * outscale;
        float yi = (xr * s + xi * c) * outscale;
        *(__half2*)&oh[(size_t)row * DIM + i0] = {__float2half(yr), __float2half(yi)};
    }
}

// ---- persistent fp16 flash attention: q-tile 64, 128t, 2 CTAs/SM -----------
// Single-precision Q, K, V, P (error-budget traded for half the MMA work).
// Smem/CTA: Q 16K @0; K-ring 2x16K @16384; V-ring 3x16K @49152; slot @98304.
#define ATT_Q    0
#define ATT_K    16384
#define ATT_V    49152
#define ATT_WS   98304
#define ATT_SMEM (98304 + 32)

__global__ __launch_bounds__(128, 2) void attention_hmma(
    const __half* __restrict__ Qh,
    const __half* __restrict__ Kh, const __half* __restrict__ Vh,
    __half* __restrict__ Oh, __half* __restrict__ Ol) {
    extern __shared__ char dsm[];
    uint32_t sbase = smem_u32(dsm);
    int* wslot = (int*)(dsm + ATT_WS);

    int tid = threadIdx.x, wid = tid >> 5, lane = tid & 31;

    int a_r = wid * 16 + (lane & 7) + ((lane >> 3) & 1) * 8;
    int a_half = lane >> 4;
    int b_r = ((lane >> 4) & 1) * 8 + (lane & 7);
    int b_half = (lane >> 3) & 1;
    int v_r = (lane & 15);
    int vg = (lane >> 4);

    for (;;) {
        if (tid == 0) wslot[0] = atomicAdd(&g_work[1], 1);
        __syncthreads();
        int item = wslot[0];
        if (item >= N_ITEM) return;
        int qb = N_QB - 1 - item / NH;   // heavy-first
        int h = item % NH;
        int q0 = qb * 64;

        // ---- load Q (single), 64 rows x 256B, subtile layout ----
        {
            const __half* src = Qh + (size_t)q0 * DIM + h * HD;
            uint32_t dst = sbase + ATT_Q;
#pragma unroll
            for (int it = 0; it < 8; it++) {
                int idx = it * 128 + tid;
                int r = idx >> 4, gg = idx & 15;
                uint32_t off = (uint32_t)((gg >> 3) * 8192) + SWZ128((uint32_t)(r * 128 + (gg & 7) * 16));
                CP_ASYNC16(dst + off, src + (size_t)r * DIM + gg * 8);
            }
            CP_COMMIT();
        }

        auto load_kv = [&](int t) {
            int k0 = t * 64;
            uint32_t kdst = sbase + ATT_K + (uint32_t)(t & 1) * 16384;
            uint32_t vdst = sbase + ATT_V + (uint32_t)(t % 3) * 16384;
            const __half* ksrc = Kh + (size_t)k0 * DIM + h * HD;
            const __half* vsrc = Vh + (size_t)k0 * DIM + h * HD;
#pragma unroll
            for (int it = 0; it < 8; it++) {
                int idx = it * 128 + tid;
                int r = idx >> 4, gg = idx & 15;
                uint32_t off = (uint32_t)((gg >> 3) * 8192) + SWZ128((uint32_t)(r * 128 + (gg & 7) * 16));
                CP_ASYNC16(kdst + off, ksrc + (size_t)r * DIM + gg * 8);
                CP_ASYNC16(vdst + off, vsrc + (size_t)r * DIM + gg * 8);
            }
        };

        float O[16][4];
#pragma unroll
        for (int i = 0; i < 16; i++)
#pragma unroll
            for (int j = 0; j < 4; j++) O[i][j] = 0.f;
        float m0 = -1e30f, m1 = -1e30f, l0 = 0.f, l1 = 0.f;
        uint32_t PhP[4][4];

        int r0g = q0 + wid * 16 + (lane >> 2);
        int fr0 = r0g / FRAME, fr1 = (r0g + 8) / FRAME;
        int blkmin_f = q0 / FRAME;
        int fqmax = (q0 + 63) / FRAME;
        int ntile = ((fqmax + 1) * FRAME + 63) >> 6;

        load_kv(0); CP_COMMIT();
        load_kv(1); CP_COMMIT();

        for (int t = 0; t < ntile; t++) {
            if (t == ntile - 1) CP_WAIT0(); else CP_WAIT1();
            __syncthreads();

            int k0 = t * 64;
            uint32_t bKh = sbase + ATT_K + (uint32_t)(t & 1) * 16384;

            // ---- S = Q K^T (single term) ----
            float S[8][4];
#pragma unroll
            for (int i = 0; i < 8; i++)
#pragma unroll
                for (int j = 0; j < 4; j++) S[i][j] = 0.f;

#pragma unroll
            for (int ks = 0; ks < 8; ks++) {
                uint32_t qa[4], kh4[16];
                uint32_t gq16 = (uint32_t)(((ks & 3) * 2 + a_half) * 16);
                uint32_t aoff = (uint32_t)((ks >> 2) * 8192) + SWZ128((uint32_t)(a_r * 128) + gq16);
                ldsm4(qa, sbase + ATT_Q + aoff);
                uint32_t gk16 = (uint32_t)(((ks & 3) * 2 + b_half) * 16);
#pragma unroll
                for (int nb = 0; nb < 4; nb++) {
                    uint32_t boff = (uint32_t)((ks >> 2) * 8192) +
                                    SWZ128((uint32_t)((nb * 16 + b_r) * 128) + gk16);
                    ldsm4(&kh4[nb * 4], bKh + boff);
                }
#pragma unroll
                for (int nf = 0; nf < 8; nf++) mma16816(S[nf], qa, &kh4[nf * 2]);
            }

            // ---- delayed PV (single term) ----
            if (t > 0) {
                uint32_t bVh = sbase + ATT_V + (uint32_t)((t - 1) % 3) * 16384;
#pragma unroll
                for (int j = 0; j < 4; j++) {
#pragma unroll
                    for (int dp = 0; dp < 4; dp++) {
                        int db0 = 2 * dp, db1 = 2 * dp + 1;
                        uint32_t row = (uint32_t)((j * 16 + v_r) * 128);
                        uint32_t voff0 = (uint32_t)((db0 >> 2) * 8192) +
                                         SWZ128(row + (uint32_t)(((db0 & 3) * 2 + vg) * 16));
                        uint32_t voff1 = (uint32_t)((db1 >> 2) * 8192) +
                                         SWZ128(row + (uint32_t)(((db1 & 3) * 2 + vg) * 16));
                        uint32_t vh_a[4], vh_b[4];
                        ldsm4t(vh_a, bVh + voff0);
                        ldsm4t(vh_b, bVh + voff1);
                        mma16816(O[4 * dp + 0], PhP[j], &vh_a[0]);
                        mma16816(O[4 * dp + 1], PhP[j], &vh_a[2]);
                        mma16816(O[4 * dp + 2], PhP[j], &vh_b[0]);
                        mma16816(O[4 * dp + 3], PhP[j], &vh_b[2]);
                    }
                }
            }

            // ---- mask ----
            if ((k0 + 63) / FRAME > blkmin_f) {
#pragma unroll
                for (int nf = 0; nf < 8; nf++) {
                    int c = k0 + nf * 8 + 2 * (lane & 3);
                    int cf0 = c / FRAME, cf1 = (c + 1) / FRAME;
                    if (cf0 > fr0) S[nf][0] = -1e30f;
                    if (cf1 > fr0) S[nf][1] = -1e30f;
                    if (cf0 > fr1) S[nf][2] = -1e30f;
                    if (cf1 > fr1) S[nf][3] = -1e30f;
                }
            }

            // ---- online softmax ----
            float mx0 = -1e30f, mx1 = -1e30f;
#pragma unroll
            for (int nf = 0; nf < 8; nf++) {
                mx0 = fmaxf(mx0, fmaxf(S[nf][0], S[nf][1]));
                mx1 = fmaxf(mx1, fmaxf(S[nf][2], S[nf][3]));
            }
            mx0 = fmaxf(mx0, __shfl_xor_sync(0xffffffffu, mx0, 1));
            mx0 = fmaxf(mx0, __shfl_xor_sync(0xffffffffu, mx0, 2));
            mx1 = fmaxf(mx1, __shfl_xor_sync(0xffffffffu, mx1, 1));
            mx1 = fmaxf(mx1, __shfl_xor_sync(0xffffffffu, mx1, 2));
            float mn0 = fmaxf(m0, mx0), mn1 = fmaxf(m1, mx1);
            float al0 = __expf(m0 - mn0), al1 = __expf(m1 - mn1);
            m0 = mn0; m1 = mn1;
#pragma unroll
            for (int i = 0; i < 16; i++) {
                O[i][0] *= al0; O[i][1] *= al0;
                O[i][2] *= al1; O[i][3] *= al1;
            }

            float ps0 = 0.f, ps1 = 0.f;
#pragma unroll
            for (int j = 0; j < 4; j++) {
                float p00 = __expf(S[2 * j][0] - mn0);
                float p01 = __expf(S[2 * j][1] - mn0);
                float p02 = __expf(S[2 * j][2] - mn1);
                float p03 = __expf(S[2 * j][3] - mn1);
                float p10 = __expf(S[2 * j + 1][0] - mn0);
                float p11 = __expf(S[2 * j + 1][1] - mn0);
                float p12 = __expf(S[2 * j + 1][2] - mn1);
                float p13 = __expf(S[2 * j + 1][3] - mn1);
                ps0 += (p00 + p01) + (p10 + p11);
                ps1 += (p02 + p03) + (p12 + p13);
                PhP[j][0] = pack_f16(p00, p01);
                PhP[j][1] = pack_f16(p02, p03);
                PhP[j][2] = pack_f16(p10, p11);
                PhP[j][3] = pack_f16(p12, p13);
            }
            ps0 += __shfl_xor_sync(0xffffffffu, ps0, 1);
            ps0 += __shfl_xor_sync(0xffffffffu, ps0, 2);
            ps1 += __shfl_xor_sync(0xffffffffu, ps1, 1);
            ps1 += __shfl_xor_sync(0xffffffffu, ps1, 2);
            l0 = l0 * al0 + ps0;
            l1 = l1 * al1 + ps1;

            __syncthreads();
            if (t + 2 < ntile) { load_kv(t + 2); CP_COMMIT(); }
        }

        // ---- final PV ----
        {
            uint32_t bVh = sbase + ATT_V + (uint32_t)((ntile - 1) % 3) * 16384;
#pragma unroll
            for (int j = 0; j < 4; j++) {
#pragma unroll
                for (int dp = 0; dp < 4; dp++) {
                    int db0 = 2 * dp, db1 = 2 * dp + 1;
                    uint32_t row = (uint32_t)((j * 16 + v_r) * 128);
                    uint32_t voff0 = (uint32_t)((db0 >> 2) * 8192) +
                                     SWZ128(row + (uint32_t)(((db0 & 3) * 2 + vg) * 16));
                    uint32_t voff1 = (uint32_t)((db1 >> 2) * 8192) +
                                     SWZ128(row + (uint32_t)(((db1 & 3) * 2 + vg) * 16));
                    uint32_t vh_a[4], vh_b[4];
                    ldsm4t(vh_a, bVh + voff0);
                    ldsm4t(vh_b, bVh + voff1);
                    mma16816(O[4 * dp + 0], PhP[j], &vh_a[0]);
                    mma16816(O[4 * dp + 1], PhP[j], &vh_a[2]);
                    mma16816(O[4 * dp + 2], PhP[j], &vh_b[0]);
                    mma16816(O[4 * dp + 3], PhP[j], &vh_b[2]);
                }
            }
        }

        // ---- epilogue: normalize, split to fp16 hi/lo, store ----
        float inv0 = 1.0f / l0, inv1 = 1.0f / l1;
        int row0 = q0 + wid * 16 + (lane >> 2);
#pragma unroll
        for (int nf = 0; nf < 16; nf++) {
            int col = h * HD + nf * 8 + 2 * (lane & 3);
            float o00 = O[nf][0] * inv0, o01 = O[nf][1] * inv0;
            float o10 = O[nf][2] * inv1, o11 = O[nf][3] * inv1;
            uint32_t h0 = pack_f16(o00, o01);
            uint32_t h1 = pack_f16(o10, o11);
            __half2 hh0 = *(__half2*)&h0;
            __half2 hh1 = *(__half2*)&h1;
            uint32_t lo0 = pack_f16(o00 - __half2float(hh0.x), o01 - __half2float(hh0.y));
            uint32_t lo1 = pack_f16(o10 - __half2float(hh1.x), o11 - __half2float(hh1.y));
            *(uint32_t*)&Oh[(size_t)row0 * DIM + col] = h0;
            *(uint32_t*)&Ol[(size_t)row0 * DIM + col] = lo0;
            *(uint32_t*)&Oh[(size_t)(row0 + 8) * DIM + col] = h1;
            *(uint32_t*)&Ol[(size_t)(row0 + 8) * DIM + col] = lo1;
        }
    }
}

// ---------------- launch ----------------
extern "C" void kernel_launch(void* const* d_in, const int* in_sizes, int n_in,
                              void* d_out, int out_size) {
    const float* x  = (const float*)d_in[0];
    const float* Wq = (const float*)d_in[1];
    const float* bq = (const float*)d_in[2];
    const float* Wk = (const float*)d_in[3];
    const float* bk = (const float*)d_in[4];
    const float* Wv = (const float*)d_in[5];
    const float* bv = (const float*)d_in[6];
    const float* Wo = (const float*)d_in[7];
    const float* bo = (const float*)d_in[8];
    const float* gq = (const float*)d_in[9];
    const float* gk = (const float*)d_in[10];
    const float* ff = (const float*)d_in[11];
    const float* fh = (const float*)d_in[12];
    const float* fw = (const float*)d_in[13];
    float* out = (float*)d_out;

    float *qp, *kp;
    __half *ah, *al, *qh, *kh, *vh, *whb;
    int* workp;
    cudaGetSymbolAddress((void**)&qp, g_q);
    cudaGetSymbolAddress((void**)&kp, g_k);
    cudaGetSymbolAddress((void**)&ah, g_ah);
    cudaGetSymbolAddress((void**)&al, g_al);
    cudaGetSymbolAddress((void**)&whb, g_wh);
    cudaGetSymbolAddress((void**)&qh, g_qh);
    cudaGetSymbolAddress((void**)&kh, g_kh);
    cudaGetSymbolAddress((void**)&vh, g_vh);
    cudaGetSymbolAddress((void**)&workp, g_work);

    cudaFuncSetAttribute(gemm_hmma,
                         cudaFuncAttributeMaxDynamicSharedMemorySize, GSMEM);
    cudaFuncSetAttribute(attention_hmma,
                         cudaFuncAttributeMaxDynamicSharedMemorySize, ATT_SMEM);

    cudaMemsetAsync(workp, 0, 4 * sizeof(int));

    angles_kernel<<<(L_TOK * NPAIR + 255) / 256, 256>>>(ff, fh, fw);

    const int NELT = L_TOK * DIM;
    split_kernel<<<(NELT / 4 + 255) / 256, 256>>>(x, ah, al, NELT);

    transpose_half4_kernel<<<dim3(DIM / 32, DIM / 32, 4), dim3(32, 8)>>>(
        Wq, Wk, Wv, Wo, whb);

    const size_t WSZ = (size_t)DIM * DIM;
    GemmArgs ga;
    ga.wh0 = whb;           ga.b0 = bq; ga.o0 = qp;
    ga.wh1 = whb + WSZ;     ga.b1 = bk; ga.o1 = kp;
    ga.wh2 = whb + 2 * WSZ; ga.b2 = bv;
    ga.ovh = vh;
    gemm_hmma<<<dim3(DIM / 128, L_TOK / 128, 3), 256, GSMEM>>>(ah, al, ga);

    rmsnorm_rope_split2<<<dim3(L_TOK, 2), 256>>>(qp, kp, gq, gk, qh, kh);

    attention_hmma<<<296, 128, ATT_SMEM>>>(qh, kh, vh, ah, al);

    GemmArgs go;
    go.wh0 = whb + 3 * WSZ; go.b0 = bo; go.o0 = out;
    go.wh1 = go.wh0; go.b1 = bo; go.o1 = out;
    go.wh2 = go.wh0; go.b2 = bo;
    go.ovh = vh;
    gemm_hmma<<<dim3(DIM / 128, L_TOK / 128, 1), 256, GSMEM>>>(ah, al, go);
}

// round 17
// speedup vs baseline: 1.7985x; 1.4089x over previous
#include <cuda_runtime.h>
#include <cuda_fp16.h>
#include <math.h>
#include <stdint.h>

#define L_TOK 3840
#define DIM   1536
#define NH    12
#define HD    128
#define FRAME 480
#define NPAIR 64
#define N_QB  60                      // 64-row q-blocks
#define N_ITEM (N_QB * NH)            // 720

// ---------------- device scratch (no allocs allowed) ----------------
__device__ float g_q[L_TOK * DIM];
__device__ float g_k[L_TOK * DIM];
__device__ float g_cos[L_TOK * NPAIR];
__device__ float g_sin[L_TOK * NPAIR];
__device__ int   g_work[4];
__device__ __half g_ah[L_TOK * DIM];      // A single fp16 (x, later attn out)
__device__ __half g_wh[4][DIM * DIM];     // W^T fp16 (single) for q,k,v,o
__device__ __half g_qh[L_TOK * DIM];      // Q single fp16
__device__ __half g_kh[L_TOK * DIM];      // K single fp16
__device__ __half g_vh[L_TOK * DIM];      // V single fp16

// =================== sm_80-era PTX helpers (valid on plain sm_103) ==========
__device__ __forceinline__ uint32_t smem_u32(const void* p) {
    uint32_t a;
    asm("{ .reg .u64 t; cvta.to.shared.u64 t, %1; cvt.u32.u64 %0, t; }" : "=r"(a) : "l"(p));
    return a;
}
#define CP_ASYNC16(dst, src) \
    asm volatile("cp.async.cg.shared.global [%0], [%1], 16;" :: "r"(dst), "l"(src))
#define CP_COMMIT() asm volatile("cp.async.commit_group;" ::: "memory")
#define CP_WAIT1()  asm volatile("cp.async.wait_group 1;" ::: "memory")
#define CP_WAIT0()  asm volatile("cp.async.wait_group 0;" ::: "memory")

__device__ __forceinline__ void ldsm4(uint32_t* r, uint32_t addr) {
    asm volatile("ldmatrix.sync.aligned.m8n8.x4.shared.b16 {%0,%1,%2,%3}, [%4];"
                 : "=r"(r[0]), "=r"(r[1]), "=r"(r[2]), "=r"(r[3]) : "r"(addr));
}
__device__ __forceinline__ void ldsm4t(uint32_t* r, uint32_t addr) {
    asm volatile("ldmatrix.sync.aligned.m8n8.x4.trans.shared.b16 {%0,%1,%2,%3}, [%4];"
                 : "=r"(r[0]), "=r"(r[1]), "=r"(r[2]), "=r"(r[3]) : "r"(addr));
}
__device__ __forceinline__ void mma16816(float* c, const uint32_t* a, const uint32_t* b) {
    asm volatile("mma.sync.aligned.m16n8k16.row.col.f32.f16.f16.f32 "
                 "{%0,%1,%2,%3}, {%4,%5,%6,%7}, {%8,%9}, {%0,%1,%2,%3};"
                 : "+f"(c[0]), "+f"(c[1]), "+f"(c[2]), "+f"(c[3])
                 : "r"(a[0]), "r"(a[1]), "r"(a[2]), "r"(a[3]), "r"(b[0]), "r"(b[1]));
}
#define SWZ128(off) ((off) ^ (((off) >> 3) & 0x70))

__device__ __forceinline__ uint32_t pack_f16(float lo, float hi) {
    uint32_t r;
    asm("cvt.rn.f16x2.f32 %0, %1, %2;" : "=r"(r) : "f"(hi), "f"(lo));
    return r;
}

// ---------------- angle table ----------------
__global__ void angles_kernel(const float* __restrict__ ff,
                              const float* __restrict__ fh,
                              const float* __restrict__ fw) {
    int idx = blockIdx.x * blockDim.x + threadIdx.x;
    if (idx >= L_TOK * NPAIR) return;
    int l = idx / NPAIR, j = idx % NPAIR;
    int f = l / FRAME, r = l % FRAME;
    int h = r / 30, w = r % 30;
    float a;
    if (j < 22)      a = ff[f * 22 + j];
    else if (j < 43) a = fh[h * 21 + (j - 22)];
    else             a = fw[w * 21 + (j - 43)];
    g_cos[idx] = cosf(a);
    g_sin[idx] = sinf(a);
}

// ---------------- convert fp32 -> fp16 single ----------------
__global__ __launch_bounds__(256) void convert_kernel(const float* __restrict__ x,
                                                      __half* __restrict__ hi, int n) {
    int i = blockIdx.x * blockDim.x + threadIdx.x;
    if (i * 4 >= n) return;
    float4 v = *(const float4*)&x[i * 4];
    __half2* ph = (__half2*)&hi[i * 4];
    ph[0] = {__float2half(v.x), __float2half(v.y)};
    ph[1] = {__float2half(v.z), __float2half(v.w)};
}

// ------- fused transpose of 4 weights [K,N] -> [N,K], single fp16 -------
__global__ __launch_bounds__(256) void transpose_half4_kernel(
    const float* __restrict__ W0, const float* __restrict__ W1,
    const float* __restrict__ W2, const float* __restrict__ W3,
    __half* __restrict__ ThBase) {
    __shared__ float t[32][33];
    int z = blockIdx.z;
    const float* W = (z == 0) ? W0 : (z == 1) ? W1 : (z == 2) ? W2 : W3;
    __half* Th = ThBase + (size_t)z * DIM * DIM;
    int tx = threadIdx.x, ty = threadIdx.y;  // 32 x 8
    int x0 = blockIdx.x * 32, y0 = blockIdx.y * 32;
#pragma unroll
    for (int i = 0; i < 32; i += 8)
        t[ty + i][tx] = W[(size_t)(y0 + ty + i) * DIM + x0 + tx];
    __syncthreads();
#pragma unroll
    for (int i = 0; i < 32; i += 8)
        Th[(size_t)(x0 + ty + i) * DIM + y0 + tx] = __float2half(t[tx][ty + i]);
}

// ------- HMMA fp16 1-term GEMM: BK=64, 256t, 2 CTAs/SM ------------------
#define GK       64
#define TILE_B   16384
#define BUF_B    (2 * TILE_B)     // A, B
#define GSMEM    (1024 + 2 * BUF_B)   // 66560 B

struct GemmArgs {
    const __half *wh0, *wh1, *wh2;
    const float *b0, *b1, *b2;
    float *o0, *o1;
    __half *ovh;
};

__global__ __launch_bounds__(256, 2) void gemm_hmma(const __half* __restrict__ Ah,
                                                    GemmArgs ga) {
    extern __shared__ char dsm[];
    uint32_t raw = smem_u32(dsm);
    uint32_t sbase = (raw + 1023u) & ~1023u;

    int tid = threadIdx.x;
    int wid = tid >> 5, lane = tid & 31;
    int m0 = blockIdx.y * 128;
    int n0 = blockIdx.x * 128;

    const __half* Bh;
    const float* bias;
    float* Cf;
    if (blockIdx.z == 0)      { Bh = ga.wh0; bias = ga.b0; Cf = ga.o0; }
    else if (blockIdx.z == 1) { Bh = ga.wh1; bias = ga.b1; Cf = ga.o1; }
    else                      { Bh = ga.wh2; bias = ga.b2; Cf = nullptr; }

    const __half* srcs[2] = {Ah, Bh};
    const int rbase[2] = {m0, n0};

    auto load_chunk = [&](int c, int buf) {
        uint32_t dst0 = sbase + (uint32_t)buf * BUF_B;
#pragma unroll
        for (int it = 0; it < 8; it++) {
            int idx = it * 256 + tid;
            int tile = idx >> 10;
            int rem = idx & 1023;
            int r = rem >> 3, g = rem & 7;
            const __half* src = srcs[tile] + (size_t)(rbase[tile] + r) * DIM + c * GK + g * 8;
            uint32_t off = (uint32_t)(r * 128 + g * 16);
            CP_ASYNC16(dst0 + (uint32_t)tile * TILE_B + SWZ128(off), src);
        }
    };

    float Creg[2][8][4];
#pragma unroll
    for (int mt = 0; mt < 2; mt++)
#pragma unroll
        for (int nf = 0; nf < 8; nf++)
#pragma unroll
            for (int j = 0; j < 4; j++) Creg[mt][nf][j] = 0.f;

    int m_base = (wid & 3) * 32;
    int n_base = (wid >> 2) * 64;
    int a_r = m_base + (lane & 7) + ((lane >> 3) & 1) * 8;
    int a_g = (lane >> 4);
    int b_r = n_base + ((lane >> 4) & 1) * 8 + (lane & 7);
    int b_g = (lane >> 3) & 1;

    const int NCH = DIM / GK;
    load_chunk(0, 0); CP_COMMIT();
    load_chunk(1, 1); CP_COMMIT();

    for (int c = 0; c < NCH; c++) {
        if (c == NCH - 1) CP_WAIT0(); else CP_WAIT1();
        __syncthreads();

        int buf = c & 1;
        uint32_t sb = sbase + (uint32_t)buf * BUF_B;
        uint32_t sAh = sb, sBh = sb + TILE_B;

#pragma unroll
        for (int ks = 0; ks < 4; ks++) {
            uint32_t ah[2][4], bh[16];
#pragma unroll
            for (int mt = 0; mt < 2; mt++) {
                uint32_t off = SWZ128((uint32_t)((a_r + mt * 16) * 128 + ((a_g + 2 * ks) * 16)));
                ldsm4(ah[mt], sAh + off);
            }
#pragma unroll
            for (int nf2 = 0; nf2 < 4; nf2++) {
                uint32_t off = SWZ128((uint32_t)((b_r + nf2 * 16) * 128 + ((b_g + 2 * ks) * 16)));
                ldsm4(&bh[nf2 * 4], sBh + off);
            }
#pragma unroll
            for (int nf = 0; nf < 8; nf++)
#pragma unroll
                for (int mt = 0; mt < 2; mt++)
                    mma16816(Creg[mt][nf], ah[mt], &bh[nf * 2]);
        }
        __syncthreads();
        if (c + 2 < NCH) { load_chunk(c + 2, buf); CP_COMMIT(); }
    }

#pragma unroll
    for (int mt = 0; mt < 2; mt++) {
#pragma unroll
        for (int nf = 0; nf < 8; nf++) {
            int r0 = m0 + m_base + mt * 16 + (lane >> 2);
            int col = n0 + n_base + nf * 8 + (lane & 3) * 2;
            float2 bv = *(const float2*)&bias[col];
            float* cc = Creg[mt][nf];
            float c00 = cc[0] + bv.x, c01 = cc[1] + bv.y;
            float c10 = cc[2] + bv.x, c11 = cc[3] + bv.y;
            if (Cf == nullptr) {
                *(uint32_t*)&ga.ovh[(size_t)r0 * DIM + col] = pack_f16(c00, c01);
                *(uint32_t*)&ga.ovh[(size_t)(r0 + 8) * DIM + col] = pack_f16(c10, c11);
            } else {
                *(float2*)&Cf[(size_t)r0 * DIM + col] = {c00, c01};
                *(float2*)&Cf[(size_t)(r0 + 8) * DIM + col] = {c10, c11};
            }
        }
    }
}

// ------- fused RMSNorm + RoPE: q -> fp16 single, k -> fp16 single -------
__global__ __launch_bounds__(256) void rmsnorm_rope_split2(
    const float* __restrict__ xq, const float* __restrict__ xk,
    const float* __restrict__ gqv, const float* __restrict__ gkv,
    __half* __restrict__ qh, __half* __restrict__ kh) {
    int row = blockIdx.x;
    int which = blockIdx.y;
    const float* xp = (which ? xk : xq) + (size_t)row * DIM;
    const float* g = which ? gkv : gqv;
    __half* oh = which ? kh : qh;
    float outscale = which ? 1.0f : 0.08838834764831845f;
    int tid = threadIdx.x;

    float ss = 0.f;
    for (int i = tid; i < DIM; i += 256) {
        float v = xp[i];
        ss += v * v;
    }
    __shared__ float red[8];
#pragma unroll
    for (int m = 16; m; m >>= 1) ss += __shfl_xor_sync(0xffffffffu, ss, m);
    if ((tid & 31) == 0) red[tid >> 5] = ss;
    __syncthreads();
    if (tid < 8) {
        float v = red[tid];
#pragma unroll
        for (int m = 4; m; m >>= 1) v += __shfl_xor_sync(0xffu, v, m);
        if (tid == 0) red[0] = rsqrtf(v * (1.0f / DIM) + 1e-6f);
    }
    __syncthreads();
    float scale = red[0];

    for (int p = tid; p < NH * NPAIR; p += 256) {
        int head = p >> 6, j = p & 63;
        int i0 = head * HD + 2 * j;
        float2 v = *(const float2*)&xp[i0];
        float2 gv = *(const float2*)&g[i0];
        float xr = v.x * scale * gv.x;
        float xi = v.y * scale * gv.y;
        float c = g_cos[row * NPAIR + j];
        float s = g_sin[row * NPAIR + j];
        float yr = (xr * c - xi * s) * outscale;
        float yi = (xr * s + xi * c) * outscale;
        *(__half2*)&oh[(size_t)row * DIM + i0] = {__float2half(yr), __float2half(yi)};
    }
}

// ---- persistent fp16 flash attention: q-tile 64, 128t, 2 CTAs/SM -----------
// Single-precision Q, K, V, P; single fp16 output.
#define ATT_Q    0
#define ATT_K    16384
#define ATT_V    49152
#define ATT_WS   98304
#define ATT_SMEM (98304 + 32)

__global__ __launch_bounds__(128, 2) void attention_hmma(
    const __half* __restrict__ Qh,
    const __half* __restrict__ Kh, const __half* __restrict__ Vh,
    __half* __restrict__ Oh) {
    extern __shared__ char dsm[];
    uint32_t sbase = smem_u32(dsm);
    int* wslot = (int*)(dsm + ATT_WS);

    int tid = threadIdx.x, wid = tid >> 5, lane = tid & 31;

    int a_r = wid * 16 + (lane & 7) + ((lane >> 3) & 1) * 8;
    int a_half = lane >> 4;
    int b_r = ((lane >> 4) & 1) * 8 + (lane & 7);
    int b_half = (lane >> 3) & 1;
    int v_r = (lane & 15);
    int vg = (lane >> 4);

    for (;;) {
        if (tid == 0) wslot[0] = atomicAdd(&g_work[1], 1);
        __syncthreads();
        int item = wslot[0];
        if (item >= N_ITEM) return;
        int qb = N_QB - 1 - item / NH;   // heavy-first
        int h = item % NH;
        int q0 = qb * 64;

        // ---- load Q (single), 64 rows x 256B, subtile layout ----
        {
            const __half* src = Qh + (size_t)q0 * DIM + h * HD;
            uint32_t dst = sbase + ATT_Q;
#pragma unroll
            for (int it = 0; it < 8; it++) {
                int idx = it * 128 + tid;
                int r = idx >> 4, gg = idx & 15;
                uint32_t off = (uint32_t)((gg >> 3) * 8192) + SWZ128((uint32_t)(r * 128 + (gg & 7) * 16));
                CP_ASYNC16(dst + off, src + (size_t)r * DIM + gg * 8);
            }
            CP_COMMIT();
        }

        auto load_kv = [&](int t) {
            int k0 = t * 64;
            uint32_t kdst = sbase + ATT_K + (uint32_t)(t & 1) * 16384;
            uint32_t vdst = sbase + ATT_V + (uint32_t)(t % 3) * 16384;
            const __half* ksrc = Kh + (size_t)k0 * DIM + h * HD;
            const __half* vsrc = Vh + (size_t)k0 * DIM + h * HD;
#pragma unroll
            for (int it = 0; it < 8; it++) {
                int idx = it * 128 + tid;
                int r = idx >> 4, gg = idx & 15;
                uint32_t off = (uint32_t)((gg >> 3) * 8192) + SWZ128((uint32_t)(r * 128 + (gg & 7) * 16));
                CP_ASYNC16(kdst + off, ksrc + (size_t)r * DIM + gg * 8);
                CP_ASYNC16(vdst + off, vsrc + (size_t)r * DIM + gg * 8);
            }
        };

        float O[16][4];
#pragma unroll
        for (int i = 0; i < 16; i++)
#pragma unroll
            for (int j = 0; j < 4; j++) O[i][j] = 0.f;
        float m0 = -1e30f, m1 = -1e30f, l0 = 0.f, l1 = 0.f;
        uint32_t PhP[4][4];

        int r0g = q0 + wid * 16 + (lane >> 2);
        int fr0 = r0g / FRAME, fr1 = (r0g + 8) / FRAME;
        int blkmin_f = q0 / FRAME;
        int fqmax = (q0 + 63) / FRAME;
        int ntile = ((fqmax + 1) * FRAME + 63) >> 6;

        load_kv(0); CP_COMMIT();
        load_kv(1); CP_COMMIT();

        for (int t = 0; t < ntile; t++) {
            if (t == ntile - 1) CP_WAIT0(); else CP_WAIT1();
            __syncthreads();

            int k0 = t * 64;
            uint32_t bKh = sbase + ATT_K + (uint32_t)(t & 1) * 16384;

            // ---- S = Q K^T (single term) ----
            float S[8][4];
#pragma unroll
            for (int i = 0; i < 8; i++)
#pragma unroll
                for (int j = 0; j < 4; j++) S[i][j] = 0.f;

#pragma unroll
            for (int ks = 0; ks < 8; ks++) {
                uint32_t qa[4], kh4[16];
                uint32_t gq16 = (uint32_t)(((ks & 3) * 2 + a_half) * 16);
                uint32_t aoff = (uint32_t)((ks >> 2) * 8192) + SWZ128((uint32_t)(a_r * 128) + gq16);
                ldsm4(qa, sbase + ATT_Q + aoff);
                uint32_t gk16 = (uint32_t)(((ks & 3) * 2 + b_half) * 16);
#pragma unroll
                for (int nb = 0; nb < 4; nb++) {
                    uint32_t boff = (uint32_t)((ks >> 2) * 8192) +
                                    SWZ128((uint32_t)((nb * 16 + b_r) * 128) + gk16);
                    ldsm4(&kh4[nb * 4], bKh + boff);
                }
#pragma unroll
                for (int nf = 0; nf < 8; nf++) mma16816(S[nf], qa, &kh4[nf * 2]);
            }

            // ---- delayed PV (single term) ----
            if (t > 0) {
                uint32_t bVh = sbase + ATT_V + (uint32_t)((t - 1) % 3) * 16384;
#pragma unroll
                for (int j = 0; j < 4; j++) {
#pragma unroll
                    for (int dp = 0; dp < 4; dp++) {
                        int db0 = 2 * dp, db1 = 2 * dp + 1;
                        uint32_t row = (uint32_t)((j * 16 + v_r) * 128);
                        uint32_t voff0 = (uint32_t)((db0 >> 2) * 8192) +
                                         SWZ128(row + (uint32_t)(((db0 & 3) * 2 + vg) * 16));
                        uint32_t voff1 = (uint32_t)((db1 >> 2) * 8192) +
                                         SWZ128(row + (uint32_t)(((db1 & 3) * 2 + vg) * 16));
                        uint32_t vh_a[4], vh_b[4];
                        ldsm4t(vh_a, bVh + voff0);
                        ldsm4t(vh_b, bVh + voff1);
                        mma16816(O[4 * dp + 0], PhP[j], &vh_a[0]);
                        mma16816(O[4 * dp + 1], PhP[j], &vh_a[2]);
                        mma16816(O[4 * dp + 2], PhP[j], &vh_b[0]);
                        mma16816(O[4 * dp + 3], PhP[j], &vh_b[2]);
                    }
                }
            }

            // ---- mask ----
            if ((k0 + 63) / FRAME > blkmin_f) {
#pragma unroll
                for (int nf = 0; nf < 8; nf++) {
                    int c = k0 + nf * 8 + 2 * (lane & 3);
                    int cf0 = c / FRAME, cf1 = (c + 1) / FRAME;
                    if (cf0 > fr0) S[nf][0] = -1e30f;
                    if (cf1 > fr0) S[nf][1] = -1e30f;
                    if (cf0 > fr1) S[nf][2] = -1e30f;
                    if (cf1 > fr1) S[nf][3] = -1e30f;
                }
            }

            // ---- online softmax ----
            float mx0 = -1e30f, mx1 = -1e30f;
#pragma unroll
            for (int nf = 0; nf < 8; nf++) {
                mx0 = fmaxf(mx0, fmaxf(S[nf][0], S[nf][1]));
                mx1 = fmaxf(mx1, fmaxf(S[nf][2], S[nf][3]));
            }
            mx0 = fmaxf(mx0, __shfl_xor_sync(0xffffffffu, mx0, 1));
            mx0 = fmaxf(mx0, __shfl_xor_sync(0xffffffffu, mx0, 2));
            mx1 = fmaxf(mx1, __shfl_xor_sync(0xffffffffu, mx1, 1));
            mx1 = fmaxf(mx1, __shfl_xor_sync(0xffffffffu, mx1, 2));
            float mn0 = fmaxf(m0, mx0), mn1 = fmaxf(m1, mx1);
            float al0 = __expf(m0 - mn0), al1 = __expf(m1 - mn1);
            m0 = mn0; m1 = mn1;
#pragma unroll
            for (int i = 0; i < 16; i++) {
                O[i][0] *= al0; O[i][1] *= al0;
                O[i][2] *= al1; O[i][3] *= al1;
            }

            float ps0 = 0.f, ps1 = 0.f;
#pragma unroll
            for (int j = 0; j < 4; j++) {
                float p00 = __expf(S[2 * j][0] - mn0);
                float p01 = __expf(S[2 * j][1] - mn0);
                float p02 = __expf(S[2 * j][2] - mn1);
                float p03 = __expf(S[2 * j][3] - mn1);
                float p10 = __expf(S[2 * j + 1][0] - mn0);
                float p11 = __expf(S[2 * j + 1][1] - mn0);
                float p12 = __expf(S[2 * j + 1][2] - mn1);
                float p13 = __expf(S[2 * j + 1][3] - mn1);
                ps0 += (p00 + p01) + (p10 + p11);
                ps1 += (p02 + p03) + (p12 + p13);
                PhP[j][0] = pack_f16(p00, p01);
                PhP[j][1] = pack_f16(p02, p03);
                PhP[j][2] = pack_f16(p10, p11);
                PhP[j][3] = pack_f16(p12, p13);
            }
            ps0 += __shfl_xor_sync(0xffffffffu, ps0, 1);
            ps0 += __shfl_xor_sync(0xffffffffu, ps0, 2);
            ps1 += __shfl_xor_sync(0xffffffffu, ps1, 1);
            ps1 += __shfl_xor_sync(0xffffffffu, ps1, 2);
            l0 = l0 * al0 + ps0;
            l1 = l1 * al1 + ps1;

            __syncthreads();
            if (t + 2 < ntile) { load_kv(t + 2); CP_COMMIT(); }
        }

        // ---- final PV ----
        {
            uint32_t bVh = sbase + ATT_V + (uint32_t)((ntile - 1) % 3) * 16384;
#pragma unroll
            for (int j = 0; j < 4; j++) {
#pragma unroll
                for (int dp = 0; dp < 4; dp++) {
                    int db0 = 2 * dp, db1 = 2 * dp + 1;
                    uint32_t row = (uint32_t)((j * 16 + v_r) * 128);
                    uint32_t voff0 = (uint32_t)((db0 >> 2) * 8192) +
                                     SWZ128(row + (uint32_t)(((db0 & 3) * 2 + vg) * 16));
                    uint32_t voff1 = (uint32_t)((db1 >> 2) * 8192) +
                                     SWZ128(row + (uint32_t)(((db1 & 3) * 2 + vg) * 16));
                    uint32_t vh_a[4], vh_b[4];
                    ldsm4t(vh_a, bVh + voff0);
                    ldsm4t(vh_b, bVh + voff1);
                    mma16816(O[4 * dp + 0], PhP[j], &vh_a[0]);
                    mma16816(O[4 * dp + 1], PhP[j], &vh_a[2]);
                    mma16816(O[4 * dp + 2], PhP[j], &vh_b[0]);
                    mma16816(O[4 * dp + 3], PhP[j], &vh_b[2]);
                }
            }
        }

        // ---- epilogue: normalize, store single fp16 ----
        float inv0 = 1.0f / l0, inv1 = 1.0f / l1;
        int row0 = q0 + wid * 16 + (lane >> 2);
#pragma unroll
        for (int nf = 0; nf < 16; nf++) {
            int col = h * HD + nf * 8 + 2 * (lane & 3);
            *(uint32_t*)&Oh[(size_t)row0 * DIM + col] =
                pack_f16(O[nf][0] * inv0, O[nf][1] * inv0);
            *(uint32_t*)&Oh[(size_t)(row0 + 8) * DIM + col] =
                pack_f16(O[nf][2] * inv1, O[nf][3] * inv1);
        }
    }
}

// ---------------- launch ----------------
extern "C" void kernel_launch(void* const* d_in, const int* in_sizes, int n_in,
                              void* d_out, int out_size) {
    const float* x  = (const float*)d_in[0];
    const float* Wq = (const float*)d_in[1];
    const float* bq = (const float*)d_in[2];
    const float* Wk = (const float*)d_in[3];
    const float* bk = (const float*)d_in[4];
    const float* Wv = (const float*)d_in[5];
    const float* bv = (const float*)d_in[6];
    const float* Wo = (const float*)d_in[7];
    const float* bo = (const float*)d_in[8];
    const float* gq = (const float*)d_in[9];
    const float* gk = (const float*)d_in[10];
    const float* ff = (const float*)d_in[11];
    const float* fh = (const float*)d_in[12];
    const float* fw = (const float*)d_in[13];
    float* out = (float*)d_out;

    float *qp, *kp;
    __half *ah, *qh, *kh, *vh, *whb;
    int* workp;
    cudaGetSymbolAddress((void**)&qp, g_q);
    cudaGetSymbolAddress((void**)&kp, g_k);
    cudaGetSymbolAddress((void**)&ah, g_ah);
    cudaGetSymbolAddress((void**)&whb, g_wh);
    cudaGetSymbolAddress((void**)&qh, g_qh);
    cudaGetSymbolAddress((void**)&kh, g_kh);
    cudaGetSymbolAddress((void**)&vh, g_vh);
    cudaGetSymbolAddress((void**)&workp, g_work);

    cudaFuncSetAttribute(gemm_hmma,
                         cudaFuncAttributeMaxDynamicSharedMemorySize, GSMEM);
    cudaFuncSetAttribute(attention_hmma,
                         cudaFuncAttributeMaxDynamicSharedMemorySize, ATT_SMEM);

    cudaMemsetAsync(workp, 0, 4 * sizeof(int));

    angles_kernel<<<(L_TOK * NPAIR + 255) / 256, 256>>>(ff, fh, fw);

    const int NELT = L_TOK * DIM;
    convert_kernel<<<(NELT / 4 + 255) / 256, 256>>>(x, ah, NELT);

    transpose_half4_kernel<<<dim3(DIM / 32, DIM / 32, 4), dim3(32, 8)>>>(
        Wq, Wk, Wv, Wo, whb);

    const size_t WSZ = (size_t)DIM * DIM;
    GemmArgs ga;
    ga.wh0 = whb;           ga.b0 = bq; ga.o0 = qp;
    ga.wh1 = whb + WSZ;     ga.b1 = bk; ga.o1 = kp;
    ga.wh2 = whb + 2 * WSZ; ga.b2 = bv;
    ga.ovh = vh;
    gemm_hmma<<<dim3(DIM / 128, L_TOK / 128, 3), 256, GSMEM>>>(ah, ga);

    rmsnorm_rope_split2<<<dim3(L_TOK, 2), 256>>>(qp, kp, gq, gk, qh, kh);

    attention_hmma<<<296, 128, ATT_SMEM>>>(qh, kh, vh, ah);

    GemmArgs go;
    go.wh0 = whb + 3 * WSZ; go.b0 = bo; go.o0 = out;
    go.wh1 = go.wh0; go.b1 = bo; go.o1 = out;
    go.wh2 = go.wh0; go.b2 = bo;
    go.ovh = vh;
    gemm_hmma<<<dim3(DIM / 128, L_TOK / 128, 1), 256, GSMEM>>>(ah, go);
}